// round 1
// baseline (speedup 1.0000x reference)
#include <cuda_runtime.h>
#include <cuda_bf16.h>
#include <cstdint>

// ---------------- problem constants ----------------
#define BB    2
#define QN    1024
#define PAST  1024
#define MAXC  4096
#define HH    32
#define HKV   8
#define DD    128
#define HID   4096
#define KLEN  (PAST + QN)          // 2048
#define NQKV  ((HH + 2*HKV) * DD)  // 6144
#define GROUPS (HH / HKV)          // 4
#define SCALE 0.08838834764831845f // 1/sqrt(128)

// output layout (floats): [attn 8388608][present_k 8388608][present_v 8388608]
#define OUT_SZ1 (BB*QN*HID)            // 8388608
#define CACHE_SZ (BB*HKV*MAXC*DD)      // 8388608

// ---------------- scratch (device globals; no allocation) ----------------
__device__ __align__(16) float g_qkv  [BB*QN*NQKV];      // 12.58M floats
__device__ __align__(16) float g_qrope[BB*HH*QN*DD];     // 8.39M
__device__ __align__(16) float g_attnO[BB*HH*QN*DD];     // 8.39M
__device__ __align__(16) float g_xo   [BB*QN*HKV*DD];    // 2.10M

// ---------------- SGEMM: C(MxN) = A(MxK) @ B(KxN), row-major, all dims %128/%8 ----------------
__global__ void sgemm128(const float* __restrict__ A, const float* __restrict__ B,
                         float* __restrict__ C, int M, int N, int K)
{
    const int BM = 128, BN = 128, BK = 8;
    __shared__ float As[BK][BM];
    __shared__ float Bs[BK][BN];
    int tid = threadIdx.x;
    int bm = blockIdx.y, bn = blockIdx.x;
    int arow = tid >> 1, acol = (tid & 1) * 4;
    int brow = tid >> 5, bcol = (tid & 31) * 4;
    int ty = tid >> 4, tx = tid & 15;
    const float* Ab = A + (long)bm * BM * K;
    const float* Bb = B + (long)bn * BN;
    float acc[8][8];
    #pragma unroll
    for (int i = 0; i < 8; i++)
        #pragma unroll
        for (int j = 0; j < 8; j++) acc[i][j] = 0.f;

    for (int kt = 0; kt < K; kt += BK) {
        float4 a = *(const float4*)(Ab + (long)arow * K + kt + acol);
        As[acol + 0][arow] = a.x; As[acol + 1][arow] = a.y;
        As[acol + 2][arow] = a.z; As[acol + 3][arow] = a.w;
        float4 bv = *(const float4*)(Bb + (long)(kt + brow) * N + bcol);
        *(float4*)&Bs[brow][bcol] = bv;
        __syncthreads();
        #pragma unroll
        for (int k = 0; k < BK; k++) {
            float ra[8], rb[8];
            #pragma unroll
            for (int i = 0; i < 8; i++) ra[i] = As[k][ty * 8 + i];
            #pragma unroll
            for (int j = 0; j < 8; j++) rb[j] = Bs[k][tx * 8 + j];
            #pragma unroll
            for (int i = 0; i < 8; i++)
                #pragma unroll
                for (int j = 0; j < 8; j++)
                    acc[i][j] += ra[i] * rb[j];
        }
        __syncthreads();
    }
    float* Cb = C + (long)(bm * BM + ty * 8) * N + bn * BN + tx * 8;
    #pragma unroll
    for (int i = 0; i < 8; i++)
        #pragma unroll
        for (int j4 = 0; j4 < 2; j4++) {
            float4 v = make_float4(acc[i][j4*4], acc[i][j4*4+1], acc[i][j4*4+2], acc[i][j4*4+3]);
            *(float4*)(Cb + (long)i * N + j4 * 4) = v;
        }
}

// ---------------- RMSNorm + RoPE + cache scatter ----------------
// grid (48, QN, BB), block 128. slot: [0,32)=q heads, [32,40)=k heads, [40,48)=v heads
__global__ void qkv_post_kernel(const float* __restrict__ rope,   // (MAXC,128): [cos|sin]
                                const int*   __restrict__ start,
                                const float* __restrict__ qw,
                                const float* __restrict__ kw,
                                float* __restrict__ out_k,
                                float* __restrict__ out_v)
{
    int slot = blockIdx.x;
    int q    = blockIdx.y;
    int b    = blockIdx.z;
    int tid  = threadIdx.x;
    long row = ((long)b * QN + q) * NQKV;
    float x = g_qkv[row + (long)slot * DD + tid];
    int pos = start[b] + q;

    if (slot >= 40) {  // v: raw scatter
        int h = slot - 40;
        out_v[(((long)b * HKV + h) * MAXC + pos) * DD + tid] = x;
        return;
    }

    __shared__ float red[4];
    __shared__ float sm[DD];
    float v2 = x * x;
    #pragma unroll
    for (int m = 16; m; m >>= 1) v2 += __shfl_xor_sync(0xffffffffu, v2, m);
    if ((tid & 31) == 0) red[tid >> 5] = v2;
    __syncthreads();
    float tot = red[0] + red[1] + red[2] + red[3];
    float scl = rsqrtf(tot * (1.f / DD) + 1e-6f);
    const float* w = (slot < 32) ? qw : kw;
    sm[tid] = x * scl * w[tid];
    __syncthreads();

    int i = (tid < 64) ? tid : tid - 64;
    float c = rope[(long)pos * DD + i];
    float s = rope[(long)pos * DD + 64 + i];
    float x1 = sm[i], x2 = sm[i + 64];
    float o = (tid < 64) ? (x1 * c - x2 * s) : (x2 * c + x1 * s);

    if (slot < 32) {
        g_qrope[(((long)b * HH + slot) * QN + q) * DD + tid] = o;
    } else {
        int h = slot - 32;
        out_k[(((long)b * HKV + h) * MAXC + pos) * DD + tid] = o;
    }
}

// ---------------- flash attention (fp32, BQ=32, BK=32, 256 thr) ----------------
__global__ void attn_kernel(const float* __restrict__ kc,   // present K (B,HKV,MAXC,D)
                            const float* __restrict__ vc)   // present V
{
    int qt = blockIdx.x, h = blockIdx.y, b = blockIdx.z;
    int kvh = h >> 2;
    int tid = threadIdx.x;        // 256
    int r   = tid >> 3;           // query row 0..31
    int sub = tid & 7;            // 0..7

    __shared__ float Qs[32][DD];
    __shared__ float Kt[DD][33];     // K transposed; V tile reuses this storage
    __shared__ float Ssm[32][33];
    float (*Vs)[DD] = reinterpret_cast<float(*)[DD]>(&Kt[0][0]);

    const float* qbase = g_qrope + (((long)b * HH + h) * QN + qt * 32) * DD;
    for (int i = tid; i < 32 * DD / 4; i += 256) {
        int rr = i >> 5, c4 = i & 31;
        float4 v = ((const float4*)qbase)[(long)rr * 32 + c4];
        *(float4*)&Qs[rr][c4 * 4] = v;
    }

    float acc[16];
    #pragma unroll
    for (int i = 0; i < 16; i++) acc[i] = 0.f;
    float mrow = -1e30f, lrow = 0.f;
    int qg = qt * 32 + r;
    int klimit = PAST + qg;                         // inclusive last key
    int ntiles = (PAST + qt * 32 + 31) / 32 + 1;
    const float* kbase = kc + ((long)b * HKV + kvh) * MAXC * DD;
    const float* vbase = vc + ((long)b * HKV + kvh) * MAXC * DD;

    for (int t = 0; t < ntiles; t++) {
        int kb = t * 32;
        __syncthreads();  // prior O-phase done before overwriting Kt
        for (int i = tid; i < 1024; i += 256) {   // 32 rows x 32 float4
            int kr = i >> 5, c4 = i & 31;
            float4 v = ((const float4*)(kbase + (long)(kb + kr) * DD))[c4];
            Kt[c4*4+0][kr] = v.x; Kt[c4*4+1][kr] = v.y;
            Kt[c4*4+2][kr] = v.z; Kt[c4*4+3][kr] = v.w;
        }
        __syncthreads();

        float s[4] = {0.f, 0.f, 0.f, 0.f};
        #pragma unroll 4
        for (int d = 0; d < DD; d++) {
            float qv = Qs[r][d];
            #pragma unroll
            for (int j = 0; j < 4; j++) s[j] += qv * Kt[d][sub + 8 * j];
        }
        float mt = -1e30f;
        #pragma unroll
        for (int j = 0; j < 4; j++) {
            int k = kb + sub + 8 * j;
            s[j] = (k <= klimit) ? s[j] * SCALE : -1e30f;
            mt = fmaxf(mt, s[j]);
        }
        mt = fmaxf(mt, __shfl_xor_sync(0xffffffffu, mt, 1));
        mt = fmaxf(mt, __shfl_xor_sync(0xffffffffu, mt, 2));
        mt = fmaxf(mt, __shfl_xor_sync(0xffffffffu, mt, 4));
        float mnew  = fmaxf(mrow, mt);
        float alpha = __expf(mrow - mnew);
        float psum = 0.f;
        #pragma unroll
        for (int j = 0; j < 4; j++) {
            float p = __expf(s[j] - mnew);
            Ssm[r][sub + 8 * j] = p;
            psum += p;
        }
        psum += __shfl_xor_sync(0xffffffffu, psum, 1);
        psum += __shfl_xor_sync(0xffffffffu, psum, 2);
        psum += __shfl_xor_sync(0xffffffffu, psum, 4);
        lrow = lrow * alpha + psum;
        mrow = mnew;
        #pragma unroll
        for (int i = 0; i < 16; i++) acc[i] *= alpha;

        __syncthreads();  // Kt reads done; load V over it
        for (int i = tid; i < 1024; i += 256) {
            int kr = i >> 5, c4 = i & 31;
            float4 v = ((const float4*)(vbase + (long)(kb + kr) * DD))[c4];
            *(float4*)&Vs[kr][c4 * 4] = v;
        }
        __syncthreads();

        #pragma unroll 4
        for (int kk = 0; kk < 32; kk++) {
            float p = Ssm[r][kk];
            #pragma unroll
            for (int dd = 0; dd < 16; dd++)
                acc[dd] += p * Vs[kk][sub + 8 * dd];
        }
    }
    float inv = 1.f / lrow;
    float* ob = g_attnO + (((long)b * HH + h) * QN + qg) * DD;
    #pragma unroll
    for (int dd = 0; dd < 16; dd++) ob[sub + 8 * dd] = acc[dd] * inv;
}

// ---------------- group sum over the 4 heads of each kv group ----------------
__global__ void group_sum_kernel()
{
    long i = (long)blockIdx.x * 256 + threadIdx.x;  // over B*QN*HKV*DD
    if (i >= (long)BB * QN * HKV * DD) return;
    int d = (int)(i & (DD - 1));
    long t = i >> 7;
    int kvh = (int)(t & (HKV - 1));
    t >>= 3;
    int q = (int)(t % QN);
    int b = (int)(t / QN);
    float sum = 0.f;
    #pragma unroll
    for (int g = 0; g < GROUPS; g++)
        sum += g_attnO[(((long)b * HH + kvh * GROUPS + g) * QN + q) * DD + d];
    g_xo[i] = sum;
}

// ---------------- launch ----------------
static float* sym_addr(const void* sym) {
    void* p = nullptr;
    cudaGetSymbolAddress(&p, sym);
    return (float*)p;
}

extern "C" void kernel_launch(void* const* d_in, const int* in_sizes, int n_in,
                              void* d_out, int out_size)
{
    const float* hidden = (const float*)d_in[0];
    const float* kcache = (const float*)d_in[1];
    const float* vcache = (const float*)d_in[2];
    const float* rope   = (const float*)d_in[3];
    const int*   start  = (const int*)  d_in[5];
    const float* w_qkv  = (const float*)d_in[6];
    const float* w_o    = (const float*)d_in[7];
    const float* qw     = (const float*)d_in[8];
    const float* kw     = (const float*)d_in[9];

    float* out      = (float*)d_out;
    float* out_attn = out;
    float* out_k    = out + OUT_SZ1;
    float* out_v    = out + OUT_SZ1 + CACHE_SZ;

    float* s_qkv = sym_addr(g_qkv);
    float* s_xo  = sym_addr(g_xo);

    // 1. copy caches into output (present caches), scatter overwrites new rows
    cudaMemcpyAsync(out_k, kcache, (size_t)CACHE_SZ * sizeof(float), cudaMemcpyDeviceToDevice, 0);
    cudaMemcpyAsync(out_v, vcache, (size_t)CACHE_SZ * sizeof(float), cudaMemcpyDeviceToDevice, 0);

    // 2. QKV projection: (2048 x 4096) @ (4096 x 6144)
    sgemm128<<<dim3(NQKV / 128, (BB * QN) / 128), 256>>>(hidden, w_qkv, s_qkv, BB * QN, NQKV, HID);

    // 3. RMSNorm + RoPE + scatter into present caches
    qkv_post_kernel<<<dim3(48, QN, BB), 128>>>(rope, start, qw, kw, out_k, out_v);

    // 4. flash attention -> per-head outputs
    attn_kernel<<<dim3(QN / 32, HH, BB), 256>>>(out_k, out_v);

    // 5. group-sum (B,HKV,4,Q,D) -> (B,Q,HKV*D)
    group_sum_kernel<<<(BB * QN * HKV * DD + 255) / 256, 256>>>();

    // 6. output projection: (2048 x 1024) @ (1024 x 4096)
    sgemm128<<<dim3(HID / 128, (BB * QN) / 128), 256>>>(s_xo, w_o, out_attn, BB * QN, HID, HKV * DD);
}

// round 3
// speedup vs baseline: 1.3934x; 1.3934x over previous
#include <cuda_runtime.h>
#include <cuda_bf16.h>
#include <cstdint>

// ---------------- problem constants ----------------
#define BB    2
#define QN    1024
#define PAST  1024
#define MAXC  4096
#define HH    32
#define HKV   8
#define DD    128
#define HID   4096
#define NQKV  ((HH + 2*HKV) * DD)  // 6144
#define GROUPS (HH / HKV)
#define SCALE 0.08838834764831845f

#define OUT_SZ1 (BB*QN*HID)
#define CACHE_SZ (BB*HKV*MAXC*DD)

// ---------------- scratch (device globals) ----------------
__device__ __align__(16) float g_qkv  [BB*QN*NQKV];
__device__ __align__(16) float g_qrope[BB*HH*QN*DD];
__device__ __align__(16) float g_attnO[BB*HH*QN*DD];

__device__ __align__(16) __nv_bfloat16 gA_hi [BB*QN*HID];
__device__ __align__(16) __nv_bfloat16 gA_lo [BB*QN*HID];
__device__ __align__(16) __nv_bfloat16 gWq_hi[NQKV*HID];    // transposed [N][K]
__device__ __align__(16) __nv_bfloat16 gWq_lo[NQKV*HID];
__device__ __align__(16) __nv_bfloat16 gWo_hi[HID*HKV*DD];  // transposed [4096][1024]
__device__ __align__(16) __nv_bfloat16 gWo_lo[HID*HKV*DD];
__device__ __align__(16) __nv_bfloat16 gXo_hi[BB*QN*HKV*DD];
__device__ __align__(16) __nv_bfloat16 gXo_lo[BB*QN*HKV*DD];

// ================= PTX helpers (portable: sm_80+ subset) =================
__device__ __forceinline__ uint32_t smem_u32(const void* p) {
    uint32_t a;
    asm("{ .reg .u64 t; cvta.to.shared.u64 t, %1; cvt.u32.u64 %0, t; }" : "=r"(a) : "l"(p));
    return a;
}
__device__ __forceinline__ void ldm_x4(uint32_t* r, uint32_t addr) {
    asm volatile("ldmatrix.sync.aligned.m8n8.x4.shared.b16 {%0,%1,%2,%3}, [%4];"
                 : "=r"(r[0]), "=r"(r[1]), "=r"(r[2]), "=r"(r[3]) : "r"(addr));
}
__device__ __forceinline__ void mma_bf16(float* d, const uint32_t* a, const uint32_t* b) {
    asm volatile(
        "mma.sync.aligned.m16n8k16.row.col.f32.bf16.bf16.f32 "
        "{%0,%1,%2,%3}, {%4,%5,%6,%7}, {%8,%9}, {%0,%1,%2,%3};"
        : "+f"(d[0]), "+f"(d[1]), "+f"(d[2]), "+f"(d[3])
        : "r"(a[0]), "r"(a[1]), "r"(a[2]), "r"(a[3]), "r"(b[0]), "r"(b[1]));
}
__device__ __forceinline__ void cp16(uint32_t dst, const void* src) {
    asm volatile("cp.async.cg.shared.global [%0], [%1], 16;" :: "r"(dst), "l"(src));
}

// ================= hi/lo conversion kernels =================
__global__ void conv_hilo(const float* __restrict__ src,
                          __nv_bfloat16* __restrict__ hi, __nv_bfloat16* __restrict__ lo, int n) {
    int i = blockIdx.x * 256 + threadIdx.x;
    if (i >= n) return;
    float x = src[i];
    __nv_bfloat16 h = __float2bfloat16(x);
    hi[i] = h;
    lo[i] = __float2bfloat16(x - __bfloat162float(h));
}

// src [K][N] fp32 -> hi/lo [N][K] bf16
__global__ void conv_hilo_T(const float* __restrict__ src,
                            __nv_bfloat16* __restrict__ hi, __nv_bfloat16* __restrict__ lo,
                            int K, int N) {
    __shared__ float t[32][33];
    int bn = blockIdx.x * 32, bk = blockIdx.y * 32;
    int x = threadIdx.x, y = threadIdx.y;  // 32 x 8
    #pragma unroll
    for (int i = 0; i < 32; i += 8)
        t[y + i][x] = src[(long)(bk + y + i) * N + bn + x];
    __syncthreads();
    #pragma unroll
    for (int i = 0; i < 32; i += 8) {
        float v = t[x][y + i];
        long o = (long)(bn + y + i) * K + bk + x;
        __nv_bfloat16 h = __float2bfloat16(v);
        hi[o] = h;
        lo[o] = __float2bfloat16(v - __bfloat162float(h));
    }
}

// ================= warp-MMA hi/lo GEMM =================
// C[M][N] = A[M][K] @ B[N][K]^T, A/B given as bf16 hi+lo. BM=BN=128, BK=32.
#define PITCH   80                    // bytes per 32-element bf16 row (conflict-free)
#define TILE_B  (128 * PITCH)         // 10240
#define STAGE_B (4 * TILE_B)          // Ahi,Alo,Bhi,Blo
#define GEMM_SMEM (2 * STAGE_B)       // double buffered: 81920

__device__ __forceinline__ void fill_stage(
    uint32_t sb, int kt, int m0, int n0, int K,
    const __nv_bfloat16* Ahi, const __nv_bfloat16* Alo,
    const __nv_bfloat16* Bhi, const __nv_bfloat16* Blo, int tid)
{
    long k0 = (long)kt * 32;
    const __nv_bfloat16* bases[4] = {Ahi, Alo, Bhi, Blo};
    #pragma unroll
    for (int t = 0; t < 4; t++) {
        const __nv_bfloat16* bp = bases[t];
        int r0 = (t < 2) ? m0 : n0;
        #pragma unroll
        for (int i = 0; i < 2; i++) {
            int idx = tid + i * 256;          // 0..511
            int row = idx >> 2, ch = idx & 3;
            uint32_t dst = sb + t * TILE_B + row * PITCH + ch * 16;
            cp16(dst, bp + (long)(r0 + row) * K + k0 + ch * 8);
        }
    }
}

__global__ void __launch_bounds__(256) gemm_mma(
    const __nv_bfloat16* __restrict__ Ahi, const __nv_bfloat16* __restrict__ Alo,
    const __nv_bfloat16* __restrict__ Bhi, const __nv_bfloat16* __restrict__ Blo,
    float* __restrict__ C, int M, int N, int K)
{
    extern __shared__ char smraw[];
    uint32_t s0 = smem_u32(smraw);
    int tid = threadIdx.x, lane = tid & 31, wid = tid >> 5;
    int wm = wid & 3, wn = wid >> 2;              // 4 x 2 warps
    int m0 = blockIdx.y * 128, n0 = blockIdx.x * 128;

    float acc[2][8][4];
    #pragma unroll
    for (int i = 0; i < 2; i++)
        #pragma unroll
        for (int j = 0; j < 8; j++)
            #pragma unroll
            for (int k = 0; k < 4; k++) acc[i][j][k] = 0.f;

    int nk = K >> 5;
    fill_stage(s0, 0, m0, n0, K, Ahi, Alo, Bhi, Blo, tid);
    asm volatile("cp.async.commit_group;" ::: "memory");

    // per-lane ldmatrix sub-offsets
    int a_row = wm * 32 + (lane & 15);
    int a_kb  = (lane >> 4) * 16;
    int b_row = wn * 64 + (lane & 7) + (lane >> 4) * 8;
    int b_kb  = ((lane >> 3) & 1) * 16;

    for (int kt = 0; kt < nk; kt++) {
        uint32_t sb = s0 + (kt & 1) * STAGE_B;
        if (kt + 1 < nk) {
            fill_stage(s0 + ((kt + 1) & 1) * STAGE_B, kt + 1, m0, n0, K, Ahi, Alo, Bhi, Blo, tid);
            asm volatile("cp.async.commit_group;" ::: "memory");
            asm volatile("cp.async.wait_group 1;" ::: "memory");
        } else {
            asm volatile("cp.async.wait_group 0;" ::: "memory");
        }
        __syncthreads();

        #pragma unroll
        for (int ks = 0; ks < 2; ks++) {
            uint32_t a[2][2][4];   // [hi/lo][mtile][4]
            #pragma unroll
            for (int hl = 0; hl < 2; hl++)
                #pragma unroll
                for (int mt = 0; mt < 2; mt++)
                    ldm_x4(a[hl][mt],
                           sb + hl * TILE_B + (a_row + mt * 16) * PITCH + ks * 32 + a_kb);
            #pragma unroll
            for (int np = 0; np < 4; np++) {
                uint32_t bh[4], bl[4];
                uint32_t bd = sb + 2 * TILE_B + (b_row + np * 16) * PITCH + ks * 32 + b_kb;
                ldm_x4(bh, bd);
                ldm_x4(bl, bd + TILE_B);
                #pragma unroll
                for (int mt = 0; mt < 2; mt++)
                    #pragma unroll
                    for (int nt = 0; nt < 2; nt++) {
                        float* d = acc[mt][np * 2 + nt];
                        mma_bf16(d, a[0][mt], &bh[nt * 2]);   // Ah*Bh
                        mma_bf16(d, a[0][mt], &bl[nt * 2]);   // Ah*Bl
                        mma_bf16(d, a[1][mt], &bh[nt * 2]);   // Al*Bh
                    }
            }
        }
        __syncthreads();
    }

    // epilogue
    int row0 = m0 + wm * 32 + (lane >> 2);
    int col0 = n0 + wn * 64 + (lane & 3) * 2;
    #pragma unroll
    for (int mt = 0; mt < 2; mt++)
        #pragma unroll
        for (int nt = 0; nt < 8; nt++) {
            float* d = acc[mt][nt];
            long r = row0 + mt * 16;
            long c = col0 + nt * 8;
            *(float2*)(C + r * N + c)       = make_float2(d[0], d[1]);
            *(float2*)(C + (r + 8) * N + c) = make_float2(d[2], d[3]);
        }
}

// ---------------- RMSNorm + RoPE + cache scatter ----------------
__global__ void qkv_post_kernel(const float* __restrict__ rope,
                                const int*   __restrict__ start,
                                const float* __restrict__ qw,
                                const float* __restrict__ kw,
                                float* __restrict__ out_k,
                                float* __restrict__ out_v)
{
    int slot = blockIdx.x;
    int q    = blockIdx.y;
    int b    = blockIdx.z;
    int tid  = threadIdx.x;
    long row = ((long)b * QN + q) * NQKV;
    float x = g_qkv[row + (long)slot * DD + tid];
    int pos = start[b] + q;

    if (slot >= 40) {
        int h = slot - 40;
        out_v[(((long)b * HKV + h) * MAXC + pos) * DD + tid] = x;
        return;
    }

    __shared__ float red[4];
    __shared__ float sm[DD];
    float v2 = x * x;
    #pragma unroll
    for (int m = 16; m; m >>= 1) v2 += __shfl_xor_sync(0xffffffffu, v2, m);
    if ((tid & 31) == 0) red[tid >> 5] = v2;
    __syncthreads();
    float tot = red[0] + red[1] + red[2] + red[3];
    float scl = rsqrtf(tot * (1.f / DD) + 1e-6f);
    const float* w = (slot < 32) ? qw : kw;
    sm[tid] = x * scl * w[tid];
    __syncthreads();

    int i = (tid < 64) ? tid : tid - 64;
    float c = rope[(long)pos * DD + i];
    float s = rope[(long)pos * DD + 64 + i];
    float x1 = sm[i], x2 = sm[i + 64];
    float o = (tid < 64) ? (x1 * c - x2 * s) : (x2 * c + x1 * s);

    if (slot < 32) {
        g_qrope[(((long)b * HH + slot) * QN + q) * DD + tid] = o;
    } else {
        int h = slot - 32;
        out_k[(((long)b * HKV + h) * MAXC + pos) * DD + tid] = o;
    }
}

// ---------------- flash attention (fp32) ----------------
__global__ void attn_kernel(const float* __restrict__ kc,
                            const float* __restrict__ vc)
{
    int qt = blockIdx.x, h = blockIdx.y, b = blockIdx.z;
    int kvh = h >> 2;
    int tid = threadIdx.x;
    int r   = tid >> 3;
    int sub = tid & 7;

    __shared__ float Qs[32][DD];
    __shared__ float Kt[DD][33];
    __shared__ float Ssm[32][33];
    float (*Vs)[DD] = reinterpret_cast<float(*)[DD]>(&Kt[0][0]);

    const float* qbase = g_qrope + (((long)b * HH + h) * QN + qt * 32) * DD;
    for (int i = tid; i < 32 * DD / 4; i += 256) {
        int rr = i >> 5, c4 = i & 31;
        float4 v = ((const float4*)qbase)[(long)rr * 32 + c4];
        *(float4*)&Qs[rr][c4 * 4] = v;
    }

    float acc[16];
    #pragma unroll
    for (int i = 0; i < 16; i++) acc[i] = 0.f;
    float mrow = -1e30f, lrow = 0.f;
    int qg = qt * 32 + r;
    int klimit = PAST + qg;
    int ntiles = (PAST + qt * 32 + 31) / 32 + 1;
    const float* kbase = kc + ((long)b * HKV + kvh) * MAXC * DD;
    const float* vbase = vc + ((long)b * HKV + kvh) * MAXC * DD;

    for (int t = 0; t < ntiles; t++) {
        int kb = t * 32;
        __syncthreads();
        for (int i = tid; i < 1024; i += 256) {
            int kr = i >> 5, c4 = i & 31;
            float4 v = ((const float4*)(kbase + (long)(kb + kr) * DD))[c4];
            Kt[c4*4+0][kr] = v.x; Kt[c4*4+1][kr] = v.y;
            Kt[c4*4+2][kr] = v.z; Kt[c4*4+3][kr] = v.w;
        }
        __syncthreads();

        float s[4] = {0.f, 0.f, 0.f, 0.f};
        #pragma unroll 4
        for (int d = 0; d < DD; d++) {
            float qv = Qs[r][d];
            #pragma unroll
            for (int j = 0; j < 4; j++) s[j] += qv * Kt[d][sub + 8 * j];
        }
        float mt = -1e30f;
        #pragma unroll
        for (int j = 0; j < 4; j++) {
            int k = kb + sub + 8 * j;
            s[j] = (k <= klimit) ? s[j] * SCALE : -1e30f;
            mt = fmaxf(mt, s[j]);
        }
        mt = fmaxf(mt, __shfl_xor_sync(0xffffffffu, mt, 1));
        mt = fmaxf(mt, __shfl_xor_sync(0xffffffffu, mt, 2));
        mt = fmaxf(mt, __shfl_xor_sync(0xffffffffu, mt, 4));
        float mnew  = fmaxf(mrow, mt);
        float alpha = __expf(mrow - mnew);
        float psum = 0.f;
        #pragma unroll
        for (int j = 0; j < 4; j++) {
            float p = __expf(s[j] - mnew);
            Ssm[r][sub + 8 * j] = p;
            psum += p;
        }
        psum += __shfl_xor_sync(0xffffffffu, psum, 1);
        psum += __shfl_xor_sync(0xffffffffu, psum, 2);
        psum += __shfl_xor_sync(0xffffffffu, psum, 4);
        lrow = lrow * alpha + psum;
        mrow = mnew;
        #pragma unroll
        for (int i = 0; i < 16; i++) acc[i] *= alpha;

        __syncthreads();
        for (int i = tid; i < 1024; i += 256) {
            int kr = i >> 5, c4 = i & 31;
            float4 v = ((const float4*)(vbase + (long)(kb + kr) * DD))[c4];
            *(float4*)&Vs[kr][c4 * 4] = v;
        }
        __syncthreads();

        #pragma unroll 4
        for (int kk = 0; kk < 32; kk++) {
            float p = Ssm[r][kk];
            #pragma unroll
            for (int dd = 0; dd < 16; dd++)
                acc[dd] += p * Vs[kk][sub + 8 * dd];
        }
    }
    float inv = 1.f / lrow;
    float* ob = g_attnO + (((long)b * HH + h) * QN + qg) * DD;
    #pragma unroll
    for (int dd = 0; dd < 16; dd++) ob[sub + 8 * dd] = acc[dd] * inv;
}

// ---------------- group sum + hi/lo conversion ----------------
__global__ void group_sum_kernel()
{
    long i = (long)blockIdx.x * 256 + threadIdx.x;
    if (i >= (long)BB * QN * HKV * DD) return;
    int d = (int)(i & (DD - 1));
    long t = i >> 7;
    int kvh = (int)(t & (HKV - 1));
    t >>= 3;
    int q = (int)(t % QN);
    int b = (int)(t / QN);
    float sum = 0.f;
    #pragma unroll
    for (int g = 0; g < GROUPS; g++)
        sum += g_attnO[(((long)b * HH + kvh * GROUPS + g) * QN + q) * DD + d];
    __nv_bfloat16 h = __float2bfloat16(sum);
    gXo_hi[i] = h;
    gXo_lo[i] = __float2bfloat16(sum - __bfloat162float(h));
}

// ---------------- launch ----------------
static __nv_bfloat16* sym_addr_b(const void* sym) {
    void* p = nullptr;
    cudaGetSymbolAddress(&p, sym);
    return (__nv_bfloat16*)p;
}
static float* sym_addr_f(const void* sym) {
    void* p = nullptr;
    cudaGetSymbolAddress(&p, sym);
    return (float*)p;
}

extern "C" void kernel_launch(void* const* d_in, const int* in_sizes, int n_in,
                              void* d_out, int out_size)
{
    const float* hidden = (const float*)d_in[0];
    const float* kcache = (const float*)d_in[1];
    const float* vcache = (const float*)d_in[2];
    const float* rope   = (const float*)d_in[3];
    const int*   start  = (const int*)  d_in[5];
    const float* w_qkv  = (const float*)d_in[6];
    const float* w_o    = (const float*)d_in[7];
    const float* qw     = (const float*)d_in[8];
    const float* kw     = (const float*)d_in[9];

    float* out      = (float*)d_out;
    float* out_attn = out;
    float* out_k    = out + OUT_SZ1;
    float* out_v    = out + OUT_SZ1 + CACHE_SZ;

    float* s_qkv = sym_addr_f(g_qkv);
    __nv_bfloat16* sA_hi = sym_addr_b(gA_hi);  __nv_bfloat16* sA_lo = sym_addr_b(gA_lo);
    __nv_bfloat16* sWq_hi = sym_addr_b(gWq_hi); __nv_bfloat16* sWq_lo = sym_addr_b(gWq_lo);
    __nv_bfloat16* sWo_hi = sym_addr_b(gWo_hi); __nv_bfloat16* sWo_lo = sym_addr_b(gWo_lo);
    __nv_bfloat16* sXo_hi = sym_addr_b(gXo_hi); __nv_bfloat16* sXo_lo = sym_addr_b(gXo_lo);

    static int smem_set = 0;
    if (!smem_set) {
        cudaFuncSetAttribute(gemm_mma, cudaFuncAttributeMaxDynamicSharedMemorySize, GEMM_SMEM);
        smem_set = 1;
    }

    // 1. present caches
    cudaMemcpyAsync(out_k, kcache, (size_t)CACHE_SZ * sizeof(float), cudaMemcpyDeviceToDevice, 0);
    cudaMemcpyAsync(out_v, vcache, (size_t)CACHE_SZ * sizeof(float), cudaMemcpyDeviceToDevice, 0);

    // 2. hi/lo conversions
    conv_hilo<<<(BB*QN*HID + 255) / 256, 256>>>(hidden, sA_hi, sA_lo, BB*QN*HID);
    conv_hilo_T<<<dim3(NQKV / 32, HID / 32), dim3(32, 8)>>>(w_qkv, sWq_hi, sWq_lo, HID, NQKV);
    conv_hilo_T<<<dim3(HID / 32, (HKV*DD) / 32), dim3(32, 8)>>>(w_o, sWo_hi, sWo_lo, HKV*DD, HID);

    // 3. QKV projection (tensor cores): (2048 x 4096) @ (4096 x 6144)
    gemm_mma<<<dim3(NQKV / 128, (BB*QN) / 128), 256, GEMM_SMEM>>>(
        sA_hi, sA_lo, sWq_hi, sWq_lo, s_qkv, BB*QN, NQKV, HID);

    // 4. RMSNorm + RoPE + scatter
    qkv_post_kernel<<<dim3(48, QN, BB), 128>>>(rope, start, qw, kw, out_k, out_v);

    // 5. flash attention
    attn_kernel<<<dim3(QN / 32, HH, BB), 256>>>(out_k, out_v);

    // 6. group-sum + hi/lo
    group_sum_kernel<<<(BB*QN*HKV*DD + 255) / 256, 256>>>();

    // 7. output projection (tensor cores): (2048 x 1024) @ (1024 x 4096)
    gemm_mma<<<dim3(HID / 128, (BB*QN) / 128), 256, GEMM_SMEM>>>(
        sXo_hi, sXo_lo, sWo_hi, sWo_lo, out_attn, BB*QN, HID, HKV*DD);
}

// round 4
// speedup vs baseline: 3.8415x; 2.7570x over previous
#include <cuda_runtime.h>
#include <cuda_bf16.h>
#include <cstdint>

// ---------------- problem constants ----------------
#define BB    2
#define QN    1024
#define PAST  1024
#define MAXC  4096
#define HH    32
#define HKV   8
#define DD    128
#define HID   4096
#define KLEN  (PAST + QN)          // 2048
#define NQKV  ((HH + 2*HKV) * DD)  // 6144
#define GROUPS (HH / HKV)
#define SCALE 0.08838834764831845f

#define OUT_SZ1 (BB*QN*HID)
#define CACHE_SZ (BB*HKV*MAXC*DD)

// ---------------- scratch (device globals) ----------------
__device__ __align__(16) float g_qkv  [BB*QN*NQKV];
__device__ __align__(16) float g_qrope[BB*HH*QN*DD];
__device__ __align__(16) float g_attnO[BB*HH*QN*DD];

__device__ __align__(16) __nv_bfloat16 gA_hi [BB*QN*HID];
__device__ __align__(16) __nv_bfloat16 gA_lo [BB*QN*HID];
__device__ __align__(16) __nv_bfloat16 gWq_hi[NQKV*HID];
__device__ __align__(16) __nv_bfloat16 gWq_lo[NQKV*HID];
__device__ __align__(16) __nv_bfloat16 gWo_hi[HID*HKV*DD];
__device__ __align__(16) __nv_bfloat16 gWo_lo[HID*HKV*DD];
__device__ __align__(16) __nv_bfloat16 gXo_hi[BB*QN*HKV*DD];
__device__ __align__(16) __nv_bfloat16 gXo_lo[BB*QN*HKV*DD];

// attention bf16 hi/lo operands
__device__ __align__(16) __nv_bfloat16 gQ_hi [BB*HH*QN*DD];
__device__ __align__(16) __nv_bfloat16 gQ_lo [BB*HH*QN*DD];
__device__ __align__(16) __nv_bfloat16 gKc_hi[BB*HKV*KLEN*DD];
__device__ __align__(16) __nv_bfloat16 gKc_lo[BB*HKV*KLEN*DD];
__device__ __align__(16) __nv_bfloat16 gVc_hi[BB*HKV*KLEN*DD];
__device__ __align__(16) __nv_bfloat16 gVc_lo[BB*HKV*KLEN*DD];

// ================= PTX helpers (sm_80+ portable subset) =================
__device__ __forceinline__ uint32_t smem_u32(const void* p) {
    uint32_t a;
    asm("{ .reg .u64 t; cvta.to.shared.u64 t, %1; cvt.u32.u64 %0, t; }" : "=r"(a) : "l"(p));
    return a;
}
__device__ __forceinline__ void ldm_x4(uint32_t* r, uint32_t addr) {
    asm volatile("ldmatrix.sync.aligned.m8n8.x4.shared.b16 {%0,%1,%2,%3}, [%4];"
                 : "=r"(r[0]), "=r"(r[1]), "=r"(r[2]), "=r"(r[3]) : "r"(addr));
}
__device__ __forceinline__ void ldm_x4t(uint32_t* r, uint32_t addr) {
    asm volatile("ldmatrix.sync.aligned.m8n8.x4.trans.shared.b16 {%0,%1,%2,%3}, [%4];"
                 : "=r"(r[0]), "=r"(r[1]), "=r"(r[2]), "=r"(r[3]) : "r"(addr));
}
__device__ __forceinline__ void mma_bf16(float* d, const uint32_t* a, const uint32_t* b) {
    asm volatile(
        "mma.sync.aligned.m16n8k16.row.col.f32.bf16.bf16.f32 "
        "{%0,%1,%2,%3}, {%4,%5,%6,%7}, {%8,%9}, {%0,%1,%2,%3};"
        : "+f"(d[0]), "+f"(d[1]), "+f"(d[2]), "+f"(d[3])
        : "r"(a[0]), "r"(a[1]), "r"(a[2]), "r"(a[3]), "r"(b[0]), "r"(b[1]));
}
__device__ __forceinline__ void cp16(uint32_t dst, const void* src) {
    asm volatile("cp.async.cg.shared.global [%0], [%1], 16;" :: "r"(dst), "l"(src));
}
__device__ __forceinline__ uint32_t pack_bf2(float x, float y) {
    __nv_bfloat162 h;
    h.x = __float2bfloat16(x); h.y = __float2bfloat16(y);
    return *(uint32_t*)&h;
}

// ================= hi/lo conversion kernels =================
__global__ void conv_hilo(const float* __restrict__ src,
                          __nv_bfloat16* __restrict__ hi, __nv_bfloat16* __restrict__ lo, int n) {
    int i = blockIdx.x * 256 + threadIdx.x;
    if (i >= n) return;
    float x = src[i];
    __nv_bfloat16 h = __float2bfloat16(x);
    hi[i] = h;
    lo[i] = __float2bfloat16(x - __bfloat162float(h));
}

// src [K][N] fp32 -> hi/lo [N][K] bf16
__global__ void conv_hilo_T(const float* __restrict__ src,
                            __nv_bfloat16* __restrict__ hi, __nv_bfloat16* __restrict__ lo,
                            int K, int N) {
    __shared__ float t[32][33];
    int bn = blockIdx.x * 32, bk = blockIdx.y * 32;
    int x = threadIdx.x, y = threadIdx.y;
    #pragma unroll
    for (int i = 0; i < 32; i += 8)
        t[y + i][x] = src[(long)(bk + y + i) * N + bn + x];
    __syncthreads();
    #pragma unroll
    for (int i = 0; i < 32; i += 8) {
        float v = t[x][y + i];
        long o = (long)(bn + y + i) * K + bk + x;
        __nv_bfloat16 h = __float2bfloat16(v);
        hi[o] = h;
        lo[o] = __float2bfloat16(v - __bfloat162float(h));
    }
}

// Q (post-rope) * SCALE -> hi/lo
__global__ void q_hilo() {
    long i = (long)blockIdx.x * 256 + threadIdx.x;
    if (i >= (long)BB * HH * QN * DD) return;
    float x = g_qrope[i] * SCALE;
    __nv_bfloat16 h = __float2bfloat16(x);
    gQ_hi[i] = h;
    gQ_lo[i] = __float2bfloat16(x - __bfloat162float(h));
}

// present K/V caches [0,KLEN) -> hi/lo
__global__ void kv_hilo(const float* __restrict__ kc, const float* __restrict__ vc) {
    long i = (long)blockIdx.x * 256 + threadIdx.x;
    if (i >= (long)BB * HKV * KLEN * DD) return;
    int d = (int)(i & (DD - 1));
    long t = i >> 7;
    int pos = (int)(t & (KLEN - 1));
    t >>= 11;                               // t = b*HKV + h
    long src = (t * MAXC + pos) * DD + d;
    float kx = kc[src];
    __nv_bfloat16 kh = __float2bfloat16(kx);
    gKc_hi[i] = kh;
    gKc_lo[i] = __float2bfloat16(kx - __bfloat162float(kh));
    float vx = vc[src];
    __nv_bfloat16 vh = __float2bfloat16(vx);
    gVc_hi[i] = vh;
    gVc_lo[i] = __float2bfloat16(vx - __bfloat162float(vh));
}

// ================= warp-MMA hi/lo GEMM (unchanged from R3) =================
#define PITCH   80
#define TILE_B  (128 * PITCH)
#define STAGE_B (4 * TILE_B)
#define GEMM_SMEM (2 * STAGE_B)

__device__ __forceinline__ void fill_stage(
    uint32_t sb, int kt, int m0, int n0, int K,
    const __nv_bfloat16* Ahi, const __nv_bfloat16* Alo,
    const __nv_bfloat16* Bhi, const __nv_bfloat16* Blo, int tid)
{
    long k0 = (long)kt * 32;
    const __nv_bfloat16* bases[4] = {Ahi, Alo, Bhi, Blo};
    #pragma unroll
    for (int t = 0; t < 4; t++) {
        const __nv_bfloat16* bp = bases[t];
        int r0 = (t < 2) ? m0 : n0;
        #pragma unroll
        for (int i = 0; i < 2; i++) {
            int idx = tid + i * 256;
            int row = idx >> 2, ch = idx & 3;
            uint32_t dst = sb + t * TILE_B + row * PITCH + ch * 16;
            cp16(dst, bp + (long)(r0 + row) * K + k0 + ch * 8);
        }
    }
}

__global__ void __launch_bounds__(256) gemm_mma(
    const __nv_bfloat16* __restrict__ Ahi, const __nv_bfloat16* __restrict__ Alo,
    const __nv_bfloat16* __restrict__ Bhi, const __nv_bfloat16* __restrict__ Blo,
    float* __restrict__ C, int M, int N, int K)
{
    extern __shared__ char smraw[];
    uint32_t s0 = smem_u32(smraw);
    int tid = threadIdx.x, lane = tid & 31, wid = tid >> 5;
    int wm = wid & 3, wn = wid >> 2;
    int m0 = blockIdx.y * 128, n0 = blockIdx.x * 128;

    float acc[2][8][4];
    #pragma unroll
    for (int i = 0; i < 2; i++)
        #pragma unroll
        for (int j = 0; j < 8; j++)
            #pragma unroll
            for (int k = 0; k < 4; k++) acc[i][j][k] = 0.f;

    int nk = K >> 5;
    fill_stage(s0, 0, m0, n0, K, Ahi, Alo, Bhi, Blo, tid);
    asm volatile("cp.async.commit_group;" ::: "memory");

    int a_row = wm * 32 + (lane & 15);
    int a_kb  = (lane >> 4) * 16;
    int b_row = wn * 64 + (lane & 7) + (lane >> 4) * 8;
    int b_kb  = ((lane >> 3) & 1) * 16;

    for (int kt = 0; kt < nk; kt++) {
        uint32_t sb = s0 + (kt & 1) * STAGE_B;
        if (kt + 1 < nk) {
            fill_stage(s0 + ((kt + 1) & 1) * STAGE_B, kt + 1, m0, n0, K, Ahi, Alo, Bhi, Blo, tid);
            asm volatile("cp.async.commit_group;" ::: "memory");
            asm volatile("cp.async.wait_group 1;" ::: "memory");
        } else {
            asm volatile("cp.async.wait_group 0;" ::: "memory");
        }
        __syncthreads();

        #pragma unroll
        for (int ks = 0; ks < 2; ks++) {
            uint32_t a[2][2][4];
            #pragma unroll
            for (int hl = 0; hl < 2; hl++)
                #pragma unroll
                for (int mt = 0; mt < 2; mt++)
                    ldm_x4(a[hl][mt],
                           sb + hl * TILE_B + (a_row + mt * 16) * PITCH + ks * 32 + a_kb);
            #pragma unroll
            for (int np = 0; np < 4; np++) {
                uint32_t bh[4], bl[4];
                uint32_t bd = sb + 2 * TILE_B + (b_row + np * 16) * PITCH + ks * 32 + b_kb;
                ldm_x4(bh, bd);
                ldm_x4(bl, bd + TILE_B);
                #pragma unroll
                for (int mt = 0; mt < 2; mt++)
                    #pragma unroll
                    for (int nt = 0; nt < 2; nt++) {
                        float* d = acc[mt][np * 2 + nt];
                        mma_bf16(d, a[0][mt], &bh[nt * 2]);
                        mma_bf16(d, a[0][mt], &bl[nt * 2]);
                        mma_bf16(d, a[1][mt], &bh[nt * 2]);
                    }
            }
        }
        __syncthreads();
    }

    int row0 = m0 + wm * 32 + (lane >> 2);
    int col0 = n0 + wn * 64 + (lane & 3) * 2;
    #pragma unroll
    for (int mt = 0; mt < 2; mt++)
        #pragma unroll
        for (int nt = 0; nt < 8; nt++) {
            float* d = acc[mt][nt];
            long r = row0 + mt * 16;
            long c = col0 + nt * 8;
            *(float2*)(C + r * N + c)       = make_float2(d[0], d[1]);
            *(float2*)(C + (r + 8) * N + c) = make_float2(d[2], d[3]);
        }
}

// ---------------- RMSNorm + RoPE + cache scatter ----------------
__global__ void qkv_post_kernel(const float* __restrict__ rope,
                                const int*   __restrict__ start,
                                const float* __restrict__ qw,
                                const float* __restrict__ kw,
                                float* __restrict__ out_k,
                                float* __restrict__ out_v)
{
    int slot = blockIdx.x;
    int q    = blockIdx.y;
    int b    = blockIdx.z;
    int tid  = threadIdx.x;
    long row = ((long)b * QN + q) * NQKV;
    float x = g_qkv[row + (long)slot * DD + tid];
    int pos = start[b] + q;

    if (slot >= 40) {
        int h = slot - 40;
        out_v[(((long)b * HKV + h) * MAXC + pos) * DD + tid] = x;
        return;
    }

    __shared__ float red[4];
    __shared__ float sm[DD];
    float v2 = x * x;
    #pragma unroll
    for (int m = 16; m; m >>= 1) v2 += __shfl_xor_sync(0xffffffffu, v2, m);
    if ((tid & 31) == 0) red[tid >> 5] = v2;
    __syncthreads();
    float tot = red[0] + red[1] + red[2] + red[3];
    float scl = rsqrtf(tot * (1.f / DD) + 1e-6f);
    const float* w = (slot < 32) ? qw : kw;
    sm[tid] = x * scl * w[tid];
    __syncthreads();

    int i = (tid < 64) ? tid : tid - 64;
    float c = rope[(long)pos * DD + i];
    float s = rope[(long)pos * DD + 64 + i];
    float x1 = sm[i], x2 = sm[i + 64];
    float o = (tid < 64) ? (x1 * c - x2 * s) : (x2 * c + x1 * s);

    if (slot < 32) {
        g_qrope[(((long)b * HH + slot) * QN + q) * DD + tid] = o;
    } else {
        int h = slot - 32;
        out_k[(((long)b * HKV + h) * MAXC + pos) * DD + tid] = o;
    }
}

// ================= tensor-core flash attention (bf16 hi/lo) =================
// BQ=64 (4 warps x 16 rows), BK=64, D=128. smem pitch 272B/row.
#define APITCHB 272
#define AQ 64
#define ATILE (AQ * APITCHB)               // 17408 per hi or lo
#define ATTN_SMEM (6 * ATILE)              // Qh,Ql,Kh,Kl,Vh,Vl = 104448

__device__ __forceinline__ void load_tile64(uint32_t dst,
    const __nv_bfloat16* hi, const __nv_bfloat16* lo, long rowbase, int tid)
{
    #pragma unroll
    for (int i = 0; i < 8; i++) {
        int idx = tid + i * 128;
        int row = idx >> 4, ch = idx & 15;
        uint32_t d = dst + row * APITCHB + ch * 16;
        const long off = rowbase + (long)row * DD + (ch << 3);
        cp16(d, hi + off);
        cp16(d + ATILE, lo + off);
    }
}

__global__ void __launch_bounds__(128) attn_mma()
{
    extern __shared__ char smraw[];
    uint32_t sQ = smem_u32(smraw);
    uint32_t sK = sQ + 2 * ATILE;
    uint32_t sV = sK + 2 * ATILE;
    int tid = threadIdx.x, lane = tid & 31, w = tid >> 5;
    int qt = blockIdx.x, h = blockIdx.y, b = blockIdx.z;
    int kvh = h >> 2;
    int q0 = qt * 64;

    long qbase  = ((long)(b * HH + h) * QN + q0) * DD;
    long kvbase = (long)(b * HKV + kvh) * KLEN * DD;

    // prologue loads: Q tile + K chunk 0 (one commit group)
    load_tile64(sQ, gQ_hi, gQ_lo, qbase, tid);
    load_tile64(sK, gKc_hi, gKc_lo, kvbase, tid);
    asm volatile("cp.async.commit_group;" ::: "memory");

    const int nc = 17 + qt;

    float O[16][4];
    #pragma unroll
    for (int i = 0; i < 16; i++)
        #pragma unroll
        for (int j = 0; j < 4; j++) O[i][j] = 0.f;
    float m0 = -1e30f, m1 = -1e30f, l0 = 0.f, l1 = 0.f;

    const int a_row  = w * 16 + (lane & 15);
    const int a_kb   = (lane >> 4) * 16;
    const int b_row  = (lane & 7) + (lane >> 4) * 8;
    const int b_kb   = ((lane >> 3) & 1) * 16;
    const int v_row  = lane & 15;
    const int v_col  = (lane >> 4) * 8;

    for (int c = 0; c < nc; c++) {
        int kb = c * 64;
        asm volatile("cp.async.wait_group 0;" ::: "memory");
        __syncthreads();

        // V chunk c in flight during S compute
        load_tile64(sV, gVc_hi, gVc_lo, kvbase + (long)kb * DD, tid);
        asm volatile("cp.async.commit_group;" ::: "memory");

        // ---- S = Q K^T ----
        float S[8][4];
        #pragma unroll
        for (int j = 0; j < 8; j++)
            #pragma unroll
            for (int k = 0; k < 4; k++) S[j][k] = 0.f;

        #pragma unroll
        for (int ks = 0; ks < 8; ks++) {
            uint32_t ah[4], al[4];
            uint32_t qa = sQ + a_row * APITCHB + ks * 32 + a_kb;
            ldm_x4(ah, qa);
            ldm_x4(al, qa + ATILE);
            #pragma unroll
            for (int np = 0; np < 4; np++) {
                uint32_t bh[4], bl[4];
                uint32_t ka = sK + (np * 16 + b_row) * APITCHB + ks * 32 + b_kb;
                ldm_x4(bh, ka);
                ldm_x4(bl, ka + ATILE);
                #pragma unroll
                for (int nt = 0; nt < 2; nt++) {
                    float* d = S[np * 2 + nt];
                    mma_bf16(d, ah, &bh[nt * 2]);
                    mma_bf16(d, ah, &bl[nt * 2]);
                    mma_bf16(d, al, &bh[nt * 2]);
                }
            }
        }

        // ---- causal mask (only last chunk touches the diagonal) ----
        if (c == nc - 1) {
            int klim0 = PAST + q0 + w * 16 + (lane >> 2);
            int klim1 = klim0 + 8;
            #pragma unroll
            for (int j = 0; j < 8; j++) {
                int col = kb + j * 8 + (lane & 3) * 2;
                if (col > klim0)     S[j][0] = -1e30f;
                if (col + 1 > klim0) S[j][1] = -1e30f;
                if (col > klim1)     S[j][2] = -1e30f;
                if (col + 1 > klim1) S[j][3] = -1e30f;
            }
        }

        // ---- online softmax ----
        float mx0 = -1e30f, mx1 = -1e30f;
        #pragma unroll
        for (int j = 0; j < 8; j++) {
            mx0 = fmaxf(mx0, fmaxf(S[j][0], S[j][1]));
            mx1 = fmaxf(mx1, fmaxf(S[j][2], S[j][3]));
        }
        mx0 = fmaxf(mx0, __shfl_xor_sync(0xffffffffu, mx0, 1));
        mx0 = fmaxf(mx0, __shfl_xor_sync(0xffffffffu, mx0, 2));
        mx1 = fmaxf(mx1, __shfl_xor_sync(0xffffffffu, mx1, 1));
        mx1 = fmaxf(mx1, __shfl_xor_sync(0xffffffffu, mx1, 2));
        float mn0 = fmaxf(m0, mx0), mn1 = fmaxf(m1, mx1);
        float al0 = __expf(m0 - mn0), al1 = __expf(m1 - mn1);
        float r0 = 0.f, r1 = 0.f;
        #pragma unroll
        for (int j = 0; j < 8; j++) {
            S[j][0] = __expf(S[j][0] - mn0);
            S[j][1] = __expf(S[j][1] - mn0);
            S[j][2] = __expf(S[j][2] - mn1);
            S[j][3] = __expf(S[j][3] - mn1);
            r0 += S[j][0] + S[j][1];
            r1 += S[j][2] + S[j][3];
        }
        r0 += __shfl_xor_sync(0xffffffffu, r0, 1);
        r0 += __shfl_xor_sync(0xffffffffu, r0, 2);
        r1 += __shfl_xor_sync(0xffffffffu, r1, 1);
        r1 += __shfl_xor_sync(0xffffffffu, r1, 2);
        l0 = l0 * al0 + r0;
        l1 = l1 * al1 + r1;
        m0 = mn0; m1 = mn1;
        #pragma unroll
        for (int i = 0; i < 16; i++) {
            O[i][0] *= al0; O[i][1] *= al0;
            O[i][2] *= al1; O[i][3] *= al1;
        }

        // ---- P -> bf16 hi/lo A-frags ----
        uint32_t pa_h[4][4], pa_l[4][4];
        #pragma unroll
        for (int kt = 0; kt < 4; kt++) {
            int j0 = 2 * kt, j1 = 2 * kt + 1;
            float v00 = S[j0][0], v01 = S[j0][1], v02 = S[j0][2], v03 = S[j0][3];
            float v10 = S[j1][0], v11 = S[j1][1], v12 = S[j1][2], v13 = S[j1][3];
            pa_h[kt][0] = pack_bf2(v00, v01);
            pa_h[kt][1] = pack_bf2(v02, v03);
            pa_h[kt][2] = pack_bf2(v10, v11);
            pa_h[kt][3] = pack_bf2(v12, v13);
            __nv_bfloat162* hp;
            hp = (__nv_bfloat162*)&pa_h[kt][0];
            pa_l[kt][0] = pack_bf2(v00 - __bfloat162float(hp->x), v01 - __bfloat162float(hp->y));
            hp = (__nv_bfloat162*)&pa_h[kt][1];
            pa_l[kt][1] = pack_bf2(v02 - __bfloat162float(hp->x), v03 - __bfloat162float(hp->y));
            hp = (__nv_bfloat162*)&pa_h[kt][2];
            pa_l[kt][2] = pack_bf2(v10 - __bfloat162float(hp->x), v11 - __bfloat162float(hp->y));
            hp = (__nv_bfloat162*)&pa_h[kt][3];
            pa_l[kt][3] = pack_bf2(v12 - __bfloat162float(hp->x), v13 - __bfloat162float(hp->y));
        }

        __syncthreads();   // all warps done reading K tile
        if (c + 1 < nc) {
            load_tile64(sK, gKc_hi, gKc_lo, kvbase + (long)(kb + 64) * DD, tid);
            asm volatile("cp.async.commit_group;" ::: "memory");
            asm volatile("cp.async.wait_group 1;" ::: "memory");   // V_c done
        } else {
            asm volatile("cp.async.wait_group 0;" ::: "memory");
        }
        __syncthreads();

        // ---- O += P V ----
        #pragma unroll
        for (int kt = 0; kt < 4; kt++) {
            #pragma unroll
            for (int np = 0; np < 8; np++) {
                uint32_t vh[4], vl[4];
                uint32_t va = sV + (kt * 16 + v_row) * APITCHB + (np * 16 + v_col) * 2;
                ldm_x4t(vh, va);
                ldm_x4t(vl, va + ATILE);
                #pragma unroll
                for (int nt = 0; nt < 2; nt++) {
                    float* d = O[np * 2 + nt];
                    mma_bf16(d, pa_h[kt], &vh[nt * 2]);
                    mma_bf16(d, pa_h[kt], &vl[nt * 2]);
                    mma_bf16(d, pa_l[kt], &vh[nt * 2]);
                }
            }
        }
        __syncthreads();   // V reads done before next-iter V overwrite
    }

    // ---- write O / l ----
    float inv0 = 1.f / l0, inv1 = 1.f / l1;
    int row0 = q0 + w * 16 + (lane >> 2);
    float* ob = g_attnO + ((long)(b * HH + h) * QN) * DD;
    #pragma unroll
    for (int np = 0; np < 16; np++) {
        int col = np * 8 + (lane & 3) * 2;
        *(float2*)(ob + (long)row0 * DD + col)       = make_float2(O[np][0] * inv0, O[np][1] * inv0);
        *(float2*)(ob + (long)(row0 + 8) * DD + col) = make_float2(O[np][2] * inv1, O[np][3] * inv1);
    }
}

// ---------------- group sum + hi/lo conversion ----------------
__global__ void group_sum_kernel()
{
    long i = (long)blockIdx.x * 256 + threadIdx.x;
    if (i >= (long)BB * QN * HKV * DD) return;
    int d = (int)(i & (DD - 1));
    long t = i >> 7;
    int kvh = (int)(t & (HKV - 1));
    t >>= 3;
    int q = (int)(t % QN);
    int b = (int)(t / QN);
    float sum = 0.f;
    #pragma unroll
    for (int g = 0; g < GROUPS; g++)
        sum += g_attnO[(((long)b * HH + kvh * GROUPS + g) * QN + q) * DD + d];
    __nv_bfloat16 h = __float2bfloat16(sum);
    gXo_hi[i] = h;
    gXo_lo[i] = __float2bfloat16(sum - __bfloat162float(h));
}

// ---------------- launch ----------------
static __nv_bfloat16* sym_addr_b(const void* sym) {
    void* p = nullptr;
    cudaGetSymbolAddress(&p, sym);
    return (__nv_bfloat16*)p;
}
static float* sym_addr_f(const void* sym) {
    void* p = nullptr;
    cudaGetSymbolAddress(&p, sym);
    return (float*)p;
}

extern "C" void kernel_launch(void* const* d_in, const int* in_sizes, int n_in,
                              void* d_out, int out_size)
{
    const float* hidden = (const float*)d_in[0];
    const float* kcache = (const float*)d_in[1];
    const float* vcache = (const float*)d_in[2];
    const float* rope   = (const float*)d_in[3];
    const int*   start  = (const int*)  d_in[5];
    const float* w_qkv  = (const float*)d_in[6];
    const float* w_o    = (const float*)d_in[7];
    const float* qw     = (const float*)d_in[8];
    const float* kw     = (const float*)d_in[9];

    float* out      = (float*)d_out;
    float* out_attn = out;
    float* out_k    = out + OUT_SZ1;
    float* out_v    = out + OUT_SZ1 + CACHE_SZ;

    float* s_qkv = sym_addr_f(g_qkv);
    __nv_bfloat16* sA_hi = sym_addr_b(gA_hi);  __nv_bfloat16* sA_lo = sym_addr_b(gA_lo);
    __nv_bfloat16* sWq_hi = sym_addr_b(gWq_hi); __nv_bfloat16* sWq_lo = sym_addr_b(gWq_lo);
    __nv_bfloat16* sWo_hi = sym_addr_b(gWo_hi); __nv_bfloat16* sWo_lo = sym_addr_b(gWo_lo);
    __nv_bfloat16* sXo_hi = sym_addr_b(gXo_hi); __nv_bfloat16* sXo_lo = sym_addr_b(gXo_lo);

    cudaFuncSetAttribute(gemm_mma, cudaFuncAttributeMaxDynamicSharedMemorySize, GEMM_SMEM);
    cudaFuncSetAttribute(attn_mma, cudaFuncAttributeMaxDynamicSharedMemorySize, ATTN_SMEM);

    // 1. present caches
    cudaMemcpyAsync(out_k, kcache, (size_t)CACHE_SZ * sizeof(float), cudaMemcpyDeviceToDevice, 0);
    cudaMemcpyAsync(out_v, vcache, (size_t)CACHE_SZ * sizeof(float), cudaMemcpyDeviceToDevice, 0);

    // 2. hi/lo conversions for projections
    conv_hilo<<<(BB*QN*HID + 255) / 256, 256>>>(hidden, sA_hi, sA_lo, BB*QN*HID);
    conv_hilo_T<<<dim3(NQKV / 32, HID / 32), dim3(32, 8)>>>(w_qkv, sWq_hi, sWq_lo, HID, NQKV);
    conv_hilo_T<<<dim3(HID / 32, (HKV*DD) / 32), dim3(32, 8)>>>(w_o, sWo_hi, sWo_lo, HKV*DD, HID);

    // 3. QKV projection
    gemm_mma<<<dim3(NQKV / 128, (BB*QN) / 128), 256, GEMM_SMEM>>>(
        sA_hi, sA_lo, sWq_hi, sWq_lo, s_qkv, BB*QN, NQKV, HID);

    // 4. RMSNorm + RoPE + scatter
    qkv_post_kernel<<<dim3(48, QN, BB), 128>>>(rope, start, qw, kw, out_k, out_v);

    // 5. attention operand conversions
    q_hilo<<<(BB*HH*QN*DD + 255) / 256, 256>>>();
    kv_hilo<<<(BB*HKV*KLEN*DD + 255) / 256, 256>>>(out_k, out_v);

    // 6. tensor-core flash attention
    attn_mma<<<dim3(QN / 64, HH, BB), 128, ATTN_SMEM>>>();

    // 7. group-sum + hi/lo
    group_sum_kernel<<<(BB*QN*HKV*DD + 255) / 256, 256>>>();

    // 8. output projection
    gemm_mma<<<dim3(HID / 128, (BB*QN) / 128), 256, GEMM_SMEM>>>(
        sXo_hi, sXo_lo, sWo_hi, sWo_lo, out_attn, BB*QN, HID, HKV*DD);
}

// round 5
// speedup vs baseline: 4.2539x; 1.1073x over previous
#include <cuda_runtime.h>
#include <cuda_bf16.h>
#include <cstdint>

// ---------------- problem constants ----------------
#define BB    2
#define QN    1024
#define PAST  1024
#define MAXC  4096
#define HH    32
#define HKV   8
#define DD    128
#define HID   4096
#define KLEN  (PAST + QN)          // 2048
#define NQKV  ((HH + 2*HKV) * DD)  // 6144
#define GROUPS (HH / HKV)
#define SCALE 0.08838834764831845f

#define OUT_SZ1 (BB*QN*HID)
#define CACHE_SZ (BB*HKV*MAXC*DD)

// ---------------- scratch (device globals) ----------------
__device__ __align__(16) float g_qkv  [BB*QN*NQKV];
__device__ __align__(16) float g_qrope[BB*HH*QN*DD];
__device__ __align__(16) float g_attnO[BB*HH*QN*DD];

__device__ __align__(16) __nv_bfloat16 gA_hi [BB*QN*HID];
__device__ __align__(16) __nv_bfloat16 gA_lo [BB*QN*HID];
__device__ __align__(16) __nv_bfloat16 gWq_hi[NQKV*HID];
__device__ __align__(16) __nv_bfloat16 gWq_lo[NQKV*HID];
__device__ __align__(16) __nv_bfloat16 gWo_hi[HID*HKV*DD];
__device__ __align__(16) __nv_bfloat16 gWo_lo[HID*HKV*DD];
__device__ __align__(16) __nv_bfloat16 gXo_hi[BB*QN*HKV*DD];
__device__ __align__(16) __nv_bfloat16 gXo_lo[BB*QN*HKV*DD];

// attention bf16 hi/lo operands
__device__ __align__(16) __nv_bfloat16 gQ_hi [BB*HH*QN*DD];
__device__ __align__(16) __nv_bfloat16 gQ_lo [BB*HH*QN*DD];
__device__ __align__(16) __nv_bfloat16 gKc_hi[BB*HKV*KLEN*DD];
__device__ __align__(16) __nv_bfloat16 gKc_lo[BB*HKV*KLEN*DD];
__device__ __align__(16) __nv_bfloat16 gVc_hi[BB*HKV*KLEN*DD];
__device__ __align__(16) __nv_bfloat16 gVc_lo[BB*HKV*KLEN*DD];

// ================= PTX helpers (sm_80+ portable subset) =================
__device__ __forceinline__ uint32_t smem_u32(const void* p) {
    uint32_t a;
    asm("{ .reg .u64 t; cvta.to.shared.u64 t, %1; cvt.u32.u64 %0, t; }" : "=r"(a) : "l"(p));
    return a;
}
__device__ __forceinline__ void ldm_x4(uint32_t* r, uint32_t addr) {
    asm volatile("ldmatrix.sync.aligned.m8n8.x4.shared.b16 {%0,%1,%2,%3}, [%4];"
                 : "=r"(r[0]), "=r"(r[1]), "=r"(r[2]), "=r"(r[3]) : "r"(addr));
}
__device__ __forceinline__ void ldm_x4t(uint32_t* r, uint32_t addr) {
    asm volatile("ldmatrix.sync.aligned.m8n8.x4.trans.shared.b16 {%0,%1,%2,%3}, [%4];"
                 : "=r"(r[0]), "=r"(r[1]), "=r"(r[2]), "=r"(r[3]) : "r"(addr));
}
__device__ __forceinline__ void mma_bf16(float* d, const uint32_t* a, const uint32_t* b) {
    asm volatile(
        "mma.sync.aligned.m16n8k16.row.col.f32.bf16.bf16.f32 "
        "{%0,%1,%2,%3}, {%4,%5,%6,%7}, {%8,%9}, {%0,%1,%2,%3};"
        : "+f"(d[0]), "+f"(d[1]), "+f"(d[2]), "+f"(d[3])
        : "r"(a[0]), "r"(a[1]), "r"(a[2]), "r"(a[3]), "r"(b[0]), "r"(b[1]));
}
__device__ __forceinline__ void cp16(uint32_t dst, const void* src) {
    asm volatile("cp.async.cg.shared.global [%0], [%1], 16;" :: "r"(dst), "l"(src));
}
__device__ __forceinline__ uint32_t pack_bf2(float x, float y) {
    __nv_bfloat162 h;
    h.x = __float2bfloat16(x); h.y = __float2bfloat16(y);
    return *(uint32_t*)&h;
}

// ================= hi/lo conversion kernels =================
__global__ void conv_hilo(const float* __restrict__ src,
                          __nv_bfloat16* __restrict__ hi, __nv_bfloat16* __restrict__ lo, int n) {
    int i = blockIdx.x * 256 + threadIdx.x;
    if (i >= n) return;
    float x = src[i];
    __nv_bfloat16 h = __float2bfloat16(x);
    hi[i] = h;
    lo[i] = __float2bfloat16(x - __bfloat162float(h));
}

// src [K][N] fp32 -> hi/lo [N][K] bf16
__global__ void conv_hilo_T(const float* __restrict__ src,
                            __nv_bfloat16* __restrict__ hi, __nv_bfloat16* __restrict__ lo,
                            int K, int N) {
    __shared__ float t[32][33];
    int bn = blockIdx.x * 32, bk = blockIdx.y * 32;
    int x = threadIdx.x, y = threadIdx.y;
    #pragma unroll
    for (int i = 0; i < 32; i += 8)
        t[y + i][x] = src[(long)(bk + y + i) * N + bn + x];
    __syncthreads();
    #pragma unroll
    for (int i = 0; i < 32; i += 8) {
        float v = t[x][y + i];
        long o = (long)(bn + y + i) * K + bk + x;
        __nv_bfloat16 h = __float2bfloat16(v);
        hi[o] = h;
        lo[o] = __float2bfloat16(v - __bfloat162float(h));
    }
}

// Q (post-rope) * SCALE -> hi/lo
__global__ void q_hilo() {
    long i = (long)blockIdx.x * 256 + threadIdx.x;
    if (i >= (long)BB * HH * QN * DD) return;
    float x = g_qrope[i] * SCALE;
    __nv_bfloat16 h = __float2bfloat16(x);
    gQ_hi[i] = h;
    gQ_lo[i] = __float2bfloat16(x - __bfloat162float(h));
}

// present K/V caches [0,KLEN) -> hi/lo
__global__ void kv_hilo(const float* __restrict__ kc, const float* __restrict__ vc) {
    long i = (long)blockIdx.x * 256 + threadIdx.x;
    if (i >= (long)BB * HKV * KLEN * DD) return;
    int d = (int)(i & (DD - 1));
    long t = i >> 7;
    int pos = (int)(t & (KLEN - 1));
    t >>= 11;                               // t = b*HKV + h
    long src = (t * MAXC + pos) * DD + d;
    float kx = kc[src];
    __nv_bfloat16 kh = __float2bfloat16(kx);
    gKc_hi[i] = kh;
    gKc_lo[i] = __float2bfloat16(kx - __bfloat162float(kh));
    float vx = vc[src];
    __nv_bfloat16 vh = __float2bfloat16(vx);
    gVc_hi[i] = vh;
    gVc_lo[i] = __float2bfloat16(vx - __bfloat162float(vh));
}

// ================= warp-MMA hi/lo GEMM =================
#define PITCH   80
#define TILE_B  (128 * PITCH)
#define STAGE_B (4 * TILE_B)
#define GEMM_SMEM (2 * STAGE_B)

__device__ __forceinline__ void fill_stage(
    uint32_t sb, int kt, int m0, int n0, int K,
    const __nv_bfloat16* Ahi, const __nv_bfloat16* Alo,
    const __nv_bfloat16* Bhi, const __nv_bfloat16* Blo, int tid)
{
    long k0 = (long)kt * 32;
    const __nv_bfloat16* bases[4] = {Ahi, Alo, Bhi, Blo};
    #pragma unroll
    for (int t = 0; t < 4; t++) {
        const __nv_bfloat16* bp = bases[t];
        int r0 = (t < 2) ? m0 : n0;
        #pragma unroll
        for (int i = 0; i < 2; i++) {
            int idx = tid + i * 256;
            int row = idx >> 2, ch = idx & 3;
            uint32_t dst = sb + t * TILE_B + row * PITCH + ch * 16;
            cp16(dst, bp + (long)(r0 + row) * K + k0 + ch * 8);
        }
    }
}

__global__ void __launch_bounds__(256, 2) gemm_mma(
    const __nv_bfloat16* __restrict__ Ahi, const __nv_bfloat16* __restrict__ Alo,
    const __nv_bfloat16* __restrict__ Bhi, const __nv_bfloat16* __restrict__ Blo,
    float* __restrict__ C, int M, int N, int K)
{
    extern __shared__ char smraw[];
    uint32_t s0 = smem_u32(smraw);
    int tid = threadIdx.x, lane = tid & 31, wid = tid >> 5;
    int wm = wid & 3, wn = wid >> 2;
    int m0 = blockIdx.y * 128, n0 = blockIdx.x * 128;

    float acc[2][8][4];
    #pragma unroll
    for (int i = 0; i < 2; i++)
        #pragma unroll
        for (int j = 0; j < 8; j++)
            #pragma unroll
            for (int k = 0; k < 4; k++) acc[i][j][k] = 0.f;

    int nk = K >> 5;
    fill_stage(s0, 0, m0, n0, K, Ahi, Alo, Bhi, Blo, tid);
    asm volatile("cp.async.commit_group;" ::: "memory");

    int a_row = wm * 32 + (lane & 15);
    int a_kb  = (lane >> 4) * 16;
    int b_row = wn * 64 + (lane & 7) + (lane >> 4) * 8;
    int b_kb  = ((lane >> 3) & 1) * 16;

    for (int kt = 0; kt < nk; kt++) {
        uint32_t sb = s0 + (kt & 1) * STAGE_B;
        if (kt + 1 < nk) {
            fill_stage(s0 + ((kt + 1) & 1) * STAGE_B, kt + 1, m0, n0, K, Ahi, Alo, Bhi, Blo, tid);
            asm volatile("cp.async.commit_group;" ::: "memory");
            asm volatile("cp.async.wait_group 1;" ::: "memory");
        } else {
            asm volatile("cp.async.wait_group 0;" ::: "memory");
        }
        __syncthreads();

        #pragma unroll
        for (int ks = 0; ks < 2; ks++) {
            uint32_t a[2][2][4];
            #pragma unroll
            for (int hl = 0; hl < 2; hl++)
                #pragma unroll
                for (int mt = 0; mt < 2; mt++)
                    ldm_x4(a[hl][mt],
                           sb + hl * TILE_B + (a_row + mt * 16) * PITCH + ks * 32 + a_kb);
            #pragma unroll
            for (int np = 0; np < 4; np++) {
                uint32_t bh[4], bl[4];
                uint32_t bd = sb + 2 * TILE_B + (b_row + np * 16) * PITCH + ks * 32 + b_kb;
                ldm_x4(bh, bd);
                ldm_x4(bl, bd + TILE_B);
                #pragma unroll
                for (int mt = 0; mt < 2; mt++)
                    #pragma unroll
                    for (int nt = 0; nt < 2; nt++) {
                        float* d = acc[mt][np * 2 + nt];
                        mma_bf16(d, a[0][mt], &bh[nt * 2]);
                        mma_bf16(d, a[0][mt], &bl[nt * 2]);
                        mma_bf16(d, a[1][mt], &bh[nt * 2]);
                    }
            }
        }
        __syncthreads();
    }

    // epilogue: float4 stores (pairs of n-tiles are contiguous: col strides of 8)
    int row0 = m0 + wm * 32 + (lane >> 2);
    int col0 = n0 + wn * 64 + (lane & 3) * 2;
    #pragma unroll
    for (int mt = 0; mt < 2; mt++)
        #pragma unroll
        for (int nt = 0; nt < 8; nt++) {
            float* d = acc[mt][nt];
            long r = row0 + mt * 16;
            long c = col0 + nt * 8;
            *(float2*)(C + r * N + c)       = make_float2(d[0], d[1]);
            *(float2*)(C + (r + 8) * N + c) = make_float2(d[2], d[3]);
        }
}

// ---------------- RMSNorm + RoPE + cache scatter ----------------
__global__ void qkv_post_kernel(const float* __restrict__ rope,
                                const int*   __restrict__ start,
                                const float* __restrict__ qw,
                                const float* __restrict__ kw,
                                float* __restrict__ out_k,
                                float* __restrict__ out_v)
{
    int slot = blockIdx.x;
    int q    = blockIdx.y;
    int b    = blockIdx.z;
    int tid  = threadIdx.x;
    long row = ((long)b * QN + q) * NQKV;
    float x = g_qkv[row + (long)slot * DD + tid];
    int pos = start[b] + q;

    if (slot >= 40) {
        int h = slot - 40;
        out_v[(((long)b * HKV + h) * MAXC + pos) * DD + tid] = x;
        return;
    }

    __shared__ float red[4];
    __shared__ float sm[DD];
    float v2 = x * x;
    #pragma unroll
    for (int m = 16; m; m >>= 1) v2 += __shfl_xor_sync(0xffffffffu, v2, m);
    if ((tid & 31) == 0) red[tid >> 5] = v2;
    __syncthreads();
    float tot = red[0] + red[1] + red[2] + red[3];
    float scl = rsqrtf(tot * (1.f / DD) + 1e-6f);
    const float* w = (slot < 32) ? qw : kw;
    sm[tid] = x * scl * w[tid];
    __syncthreads();

    int i = (tid < 64) ? tid : tid - 64;
    float c = rope[(long)pos * DD + i];
    float s = rope[(long)pos * DD + 64 + i];
    float x1 = sm[i], x2 = sm[i + 64];
    float o = (tid < 64) ? (x1 * c - x2 * s) : (x2 * c + x1 * s);

    if (slot < 32) {
        g_qrope[(((long)b * HH + slot) * QN + q) * DD + tid] = o;
    } else {
        int h = slot - 32;
        out_k[(((long)b * HKV + h) * MAXC + pos) * DD + tid] = o;
    }
}

// ================= tensor-core flash attention (bf16 hi/lo) =================
#define APITCHB 272
#define AQ 64
#define ATILE (AQ * APITCHB)               // 17408 per hi or lo
#define ATTN_SMEM (6 * ATILE)              // Qh,Ql,Kh,Kl,Vh,Vl = 104448

__device__ __forceinline__ void load_tile64(uint32_t dst,
    const __nv_bfloat16* hi, const __nv_bfloat16* lo, long rowbase, int tid)
{
    #pragma unroll
    for (int i = 0; i < 8; i++) {
        int idx = tid + i * 128;
        int row = idx >> 4, ch = idx & 15;
        uint32_t d = dst + row * APITCHB + ch * 16;
        const long off = rowbase + (long)row * DD + (ch << 3);
        cp16(d, hi + off);
        cp16(d + ATILE, lo + off);
    }
}

__global__ void __launch_bounds__(128, 2) attn_mma()
{
    extern __shared__ char smraw[];
    uint32_t sQ = smem_u32(smraw);
    uint32_t sK = sQ + 2 * ATILE;
    uint32_t sV = sK + 2 * ATILE;
    int tid = threadIdx.x, lane = tid & 31, w = tid >> 5;
    int qt = blockIdx.x, h = blockIdx.y, b = blockIdx.z;
    int kvh = h >> 2;
    int q0 = qt * 64;

    long qbase  = ((long)(b * HH + h) * QN + q0) * DD;
    long kvbase = (long)(b * HKV + kvh) * KLEN * DD;

    load_tile64(sQ, gQ_hi, gQ_lo, qbase, tid);
    load_tile64(sK, gKc_hi, gKc_lo, kvbase, tid);
    asm volatile("cp.async.commit_group;" ::: "memory");

    const int nc = 17 + qt;

    float O[16][4];
    #pragma unroll
    for (int i = 0; i < 16; i++)
        #pragma unroll
        for (int j = 0; j < 4; j++) O[i][j] = 0.f;
    float m0 = -1e30f, m1 = -1e30f, l0 = 0.f, l1 = 0.f;

    const int a_row  = w * 16 + (lane & 15);
    const int a_kb   = (lane >> 4) * 16;
    const int b_row  = (lane & 7) + (lane >> 4) * 8;
    const int b_kb   = ((lane >> 3) & 1) * 16;
    const int v_row  = lane & 15;
    const int v_col  = (lane >> 4) * 8;

    for (int c = 0; c < nc; c++) {
        int kb = c * 64;
        asm volatile("cp.async.wait_group 0;" ::: "memory");
        __syncthreads();

        load_tile64(sV, gVc_hi, gVc_lo, kvbase + (long)kb * DD, tid);
        asm volatile("cp.async.commit_group;" ::: "memory");

        // ---- S = Q K^T ----
        float S[8][4];
        #pragma unroll
        for (int j = 0; j < 8; j++)
            #pragma unroll
            for (int k = 0; k < 4; k++) S[j][k] = 0.f;

        #pragma unroll
        for (int ks = 0; ks < 8; ks++) {
            uint32_t ah[4], al[4];
            uint32_t qa = sQ + a_row * APITCHB + ks * 32 + a_kb;
            ldm_x4(ah, qa);
            ldm_x4(al, qa + ATILE);
            #pragma unroll
            for (int np = 0; np < 4; np++) {
                uint32_t bh[4], bl[4];
                uint32_t ka = sK + (np * 16 + b_row) * APITCHB + ks * 32 + b_kb;
                ldm_x4(bh, ka);
                ldm_x4(bl, ka + ATILE);
                #pragma unroll
                for (int nt = 0; nt < 2; nt++) {
                    float* d = S[np * 2 + nt];
                    mma_bf16(d, ah, &bh[nt * 2]);
                    mma_bf16(d, ah, &bl[nt * 2]);
                    mma_bf16(d, al, &bh[nt * 2]);
                }
            }
        }

        if (c == nc - 1) {
            int klim0 = PAST + q0 + w * 16 + (lane >> 2);
            int klim1 = klim0 + 8;
            #pragma unroll
            for (int j = 0; j < 8; j++) {
                int col = kb + j * 8 + (lane & 3) * 2;
                if (col > klim0)     S[j][0] = -1e30f;
                if (col + 1 > klim0) S[j][1] = -1e30f;
                if (col > klim1)     S[j][2] = -1e30f;
                if (col + 1 > klim1) S[j][3] = -1e30f;
            }
        }

        // ---- online softmax ----
        float mx0 = -1e30f, mx1 = -1e30f;
        #pragma unroll
        for (int j = 0; j < 8; j++) {
            mx0 = fmaxf(mx0, fmaxf(S[j][0], S[j][1]));
            mx1 = fmaxf(mx1, fmaxf(S[j][2], S[j][3]));
        }
        mx0 = fmaxf(mx0, __shfl_xor_sync(0xffffffffu, mx0, 1));
        mx0 = fmaxf(mx0, __shfl_xor_sync(0xffffffffu, mx0, 2));
        mx1 = fmaxf(mx1, __shfl_xor_sync(0xffffffffu, mx1, 1));
        mx1 = fmaxf(mx1, __shfl_xor_sync(0xffffffffu, mx1, 2));
        float mn0 = fmaxf(m0, mx0), mn1 = fmaxf(m1, mx1);
        float al0 = __expf(m0 - mn0), al1 = __expf(m1 - mn1);
        float r0 = 0.f, r1 = 0.f;
        #pragma unroll
        for (int j = 0; j < 8; j++) {
            S[j][0] = __expf(S[j][0] - mn0);
            S[j][1] = __expf(S[j][1] - mn0);
            S[j][2] = __expf(S[j][2] - mn1);
            S[j][3] = __expf(S[j][3] - mn1);
            r0 += S[j][0] + S[j][1];
            r1 += S[j][2] + S[j][3];
        }
        r0 += __shfl_xor_sync(0xffffffffu, r0, 1);
        r0 += __shfl_xor_sync(0xffffffffu, r0, 2);
        r1 += __shfl_xor_sync(0xffffffffu, r1, 1);
        r1 += __shfl_xor_sync(0xffffffffu, r1, 2);
        l0 = l0 * al0 + r0;
        l1 = l1 * al1 + r1;
        m0 = mn0; m1 = mn1;
        #pragma unroll
        for (int i = 0; i < 16; i++) {
            O[i][0] *= al0; O[i][1] *= al0;
            O[i][2] *= al1; O[i][3] *= al1;
        }

        // ---- P -> bf16 hi/lo A-frags ----
        uint32_t pa_h[4][4], pa_l[4][4];
        #pragma unroll
        for (int kt = 0; kt < 4; kt++) {
            int j0 = 2 * kt, j1 = 2 * kt + 1;
            float v00 = S[j0][0], v01 = S[j0][1], v02 = S[j0][2], v03 = S[j0][3];
            float v10 = S[j1][0], v11 = S[j1][1], v12 = S[j1][2], v13 = S[j1][3];
            pa_h[kt][0] = pack_bf2(v00, v01);
            pa_h[kt][1] = pack_bf2(v02, v03);
            pa_h[kt][2] = pack_bf2(v10, v11);
            pa_h[kt][3] = pack_bf2(v12, v13);
            __nv_bfloat162* hp;
            hp = (__nv_bfloat162*)&pa_h[kt][0];
            pa_l[kt][0] = pack_bf2(v00 - __bfloat162float(hp->x), v01 - __bfloat162float(hp->y));
            hp = (__nv_bfloat162*)&pa_h[kt][1];
            pa_l[kt][1] = pack_bf2(v02 - __bfloat162float(hp->x), v03 - __bfloat162float(hp->y));
            hp = (__nv_bfloat162*)&pa_h[kt][2];
            pa_l[kt][2] = pack_bf2(v10 - __bfloat162float(hp->x), v11 - __bfloat162float(hp->y));
            hp = (__nv_bfloat162*)&pa_h[kt][3];
            pa_l[kt][3] = pack_bf2(v12 - __bfloat162float(hp->x), v13 - __bfloat162float(hp->y));
        }

        __syncthreads();
        if (c + 1 < nc) {
            load_tile64(sK, gKc_hi, gKc_lo, kvbase + (long)(kb + 64) * DD, tid);
            asm volatile("cp.async.commit_group;" ::: "memory");
            asm volatile("cp.async.wait_group 1;" ::: "memory");
        } else {
            asm volatile("cp.async.wait_group 0;" ::: "memory");
        }
        __syncthreads();

        // ---- O += P V ----
        #pragma unroll
        for (int kt = 0; kt < 4; kt++) {
            #pragma unroll
            for (int np = 0; np < 8; np++) {
                uint32_t vh[4], vl[4];
                uint32_t va = sV + (kt * 16 + v_row) * APITCHB + (np * 16 + v_col) * 2;
                ldm_x4t(vh, va);
                ldm_x4t(vl, va + ATILE);
                #pragma unroll
                for (int nt = 0; nt < 2; nt++) {
                    float* d = O[np * 2 + nt];
                    mma_bf16(d, pa_h[kt], &vh[nt * 2]);
                    mma_bf16(d, pa_h[kt], &vl[nt * 2]);
                    mma_bf16(d, pa_l[kt], &vh[nt * 2]);
                }
            }
        }
        __syncthreads();
    }

    float inv0 = 1.f / l0, inv1 = 1.f / l1;
    int row0 = q0 + w * 16 + (lane >> 2);
    float* ob = g_attnO + ((long)(b * HH + h) * QN) * DD;
    #pragma unroll
    for (int np = 0; np < 16; np++) {
        int col = np * 8 + (lane & 3) * 2;
        *(float2*)(ob + (long)row0 * DD + col)       = make_float2(O[np][0] * inv0, O[np][1] * inv0);
        *(float2*)(ob + (long)(row0 + 8) * DD + col) = make_float2(O[np][2] * inv1, O[np][3] * inv1);
    }
}

// ---------------- group sum + hi/lo conversion ----------------
__global__ void group_sum_kernel()
{
    long i = (long)blockIdx.x * 256 + threadIdx.x;
    if (i >= (long)BB * QN * HKV * DD) return;
    int d = (int)(i & (DD - 1));
    long t = i >> 7;
    int kvh = (int)(t & (HKV - 1));
    t >>= 3;
    int q = (int)(t % QN);
    int b = (int)(t / QN);
    float sum = 0.f;
    #pragma unroll
    for (int g = 0; g < GROUPS; g++)
        sum += g_attnO[(((long)b * HH + kvh * GROUPS + g) * QN + q) * DD + d];
    __nv_bfloat16 h = __float2bfloat16(sum);
    gXo_hi[i] = h;
    gXo_lo[i] = __float2bfloat16(sum - __bfloat162float(h));
}

// ---------------- launch ----------------
static __nv_bfloat16* sym_addr_b(const void* sym) {
    void* p = nullptr;
    cudaGetSymbolAddress(&p, sym);
    return (__nv_bfloat16*)p;
}
static float* sym_addr_f(const void* sym) {
    void* p = nullptr;
    cudaGetSymbolAddress(&p, sym);
    return (float*)p;
}

extern "C" void kernel_launch(void* const* d_in, const int* in_sizes, int n_in,
                              void* d_out, int out_size)
{
    const float* hidden = (const float*)d_in[0];
    const float* kcache = (const float*)d_in[1];
    const float* vcache = (const float*)d_in[2];
    const float* rope   = (const float*)d_in[3];
    const int*   start  = (const int*)  d_in[5];
    const float* w_qkv  = (const float*)d_in[6];
    const float* w_o    = (const float*)d_in[7];
    const float* qw     = (const float*)d_in[8];
    const float* kw     = (const float*)d_in[9];

    float* out      = (float*)d_out;
    float* out_attn = out;
    float* out_k    = out + OUT_SZ1;
    float* out_v    = out + OUT_SZ1 + CACHE_SZ;

    float* s_qkv = sym_addr_f(g_qkv);
    __nv_bfloat16* sA_hi = sym_addr_b(gA_hi);  __nv_bfloat16* sA_lo = sym_addr_b(gA_lo);
    __nv_bfloat16* sWq_hi = sym_addr_b(gWq_hi); __nv_bfloat16* sWq_lo = sym_addr_b(gWq_lo);
    __nv_bfloat16* sWo_hi = sym_addr_b(gWo_hi); __nv_bfloat16* sWo_lo = sym_addr_b(gWo_lo);
    __nv_bfloat16* sXo_hi = sym_addr_b(gXo_hi); __nv_bfloat16* sXo_lo = sym_addr_b(gXo_lo);

    cudaFuncSetAttribute(gemm_mma, cudaFuncAttributeMaxDynamicSharedMemorySize, GEMM_SMEM);
    cudaFuncSetAttribute(attn_mma, cudaFuncAttributeMaxDynamicSharedMemorySize, ATTN_SMEM);

    // 1. present caches
    cudaMemcpyAsync(out_k, kcache, (size_t)CACHE_SZ * sizeof(float), cudaMemcpyDeviceToDevice, 0);
    cudaMemcpyAsync(out_v, vcache, (size_t)CACHE_SZ * sizeof(float), cudaMemcpyDeviceToDevice, 0);

    // 2. hi/lo conversions for projections
    conv_hilo<<<(BB*QN*HID + 255) / 256, 256>>>(hidden, sA_hi, sA_lo, BB*QN*HID);
    conv_hilo_T<<<dim3(NQKV / 32, HID / 32), dim3(32, 8)>>>(w_qkv, sWq_hi, sWq_lo, HID, NQKV);
    conv_hilo_T<<<dim3(HID / 32, (HKV*DD) / 32), dim3(32, 8)>>>(w_o, sWo_hi, sWo_lo, HKV*DD, HID);

    // 3. QKV projection
    gemm_mma<<<dim3(NQKV / 128, (BB*QN) / 128), 256, GEMM_SMEM>>>(
        sA_hi, sA_lo, sWq_hi, sWq_lo, s_qkv, BB*QN, NQKV, HID);

    // 4. RMSNorm + RoPE + scatter
    qkv_post_kernel<<<dim3(48, QN, BB), 128>>>(rope, start, qw, kw, out_k, out_v);

    // 5. attention operand conversions
    q_hilo<<<(BB*HH*QN*DD + 255) / 256, 256>>>();
    kv_hilo<<<(BB*HKV*KLEN*DD + 255) / 256, 256>>>(out_k, out_v);

    // 6. tensor-core flash attention
    attn_mma<<<dim3(QN / 64, HH, BB), 128, ATTN_SMEM>>>();

    // 7. group-sum + hi/lo
    group_sum_kernel<<<(BB*QN*HKV*DD + 255) / 256, 256>>>();

    // 8. output projection
    gemm_mma<<<dim3(HID / 128, (BB*QN) / 128), 256, GEMM_SMEM>>>(
        sXo_hi, sXo_lo, sWo_hi, sWo_lo, out_attn, BB*QN, HID, HKV*DD);
}

// round 6
// speedup vs baseline: 4.6788x; 1.0999x over previous
#include <cuda_runtime.h>
#include <cuda_bf16.h>
#include <cstdint>

// ---------------- problem constants ----------------
#define BB    2
#define QN    1024
#define PAST  1024
#define MAXC  4096
#define HH    32
#define HKV   8
#define DD    128
#define HID   4096
#define KLEN  (PAST + QN)          // 2048
#define NQKV  ((HH + 2*HKV) * DD)  // 6144
#define GROUPS (HH / HKV)
#define SCALE 0.08838834764831845f

#define OUT_SZ1 (BB*QN*HID)
#define CACHE_SZ (BB*HKV*MAXC*DD)

// ---------------- scratch (device globals) ----------------
__device__ __align__(16) float g_qkv  [BB*QN*NQKV];
__device__ __align__(16) float g_qrope[BB*HH*QN*DD];
__device__ __align__(16) float g_attnO[BB*HH*QN*DD];

__device__ __align__(16) __nv_bfloat16 gA_hi [BB*QN*HID];
__device__ __align__(16) __nv_bfloat16 gA_lo [BB*QN*HID];
__device__ __align__(16) __nv_bfloat16 gWq_hi[NQKV*HID];
__device__ __align__(16) __nv_bfloat16 gWq_lo[NQKV*HID];
__device__ __align__(16) __nv_bfloat16 gWo_hi[HID*HKV*DD];
__device__ __align__(16) __nv_bfloat16 gWo_lo[HID*HKV*DD];
__device__ __align__(16) __nv_bfloat16 gXo_hi[BB*QN*HKV*DD];
__device__ __align__(16) __nv_bfloat16 gXo_lo[BB*QN*HKV*DD];

// attention bf16 hi/lo operands
__device__ __align__(16) __nv_bfloat16 gQ_hi [BB*HH*QN*DD];
__device__ __align__(16) __nv_bfloat16 gQ_lo [BB*HH*QN*DD];
__device__ __align__(16) __nv_bfloat16 gKc_hi[BB*HKV*KLEN*DD];
__device__ __align__(16) __nv_bfloat16 gKc_lo[BB*HKV*KLEN*DD];
__device__ __align__(16) __nv_bfloat16 gVc_hi[BB*HKV*KLEN*DD];
__device__ __align__(16) __nv_bfloat16 gVc_lo[BB*HKV*KLEN*DD];

// ================= PTX helpers (sm_80+ portable subset) =================
__device__ __forceinline__ uint32_t smem_u32(const void* p) {
    uint32_t a;
    asm("{ .reg .u64 t; cvta.to.shared.u64 t, %1; cvt.u32.u64 %0, t; }" : "=r"(a) : "l"(p));
    return a;
}
__device__ __forceinline__ void ldm_x4(uint32_t* r, uint32_t addr) {
    asm volatile("ldmatrix.sync.aligned.m8n8.x4.shared.b16 {%0,%1,%2,%3}, [%4];"
                 : "=r"(r[0]), "=r"(r[1]), "=r"(r[2]), "=r"(r[3]) : "r"(addr));
}
__device__ __forceinline__ void ldm_x4t(uint32_t* r, uint32_t addr) {
    asm volatile("ldmatrix.sync.aligned.m8n8.x4.trans.shared.b16 {%0,%1,%2,%3}, [%4];"
                 : "=r"(r[0]), "=r"(r[1]), "=r"(r[2]), "=r"(r[3]) : "r"(addr));
}
__device__ __forceinline__ void mma_bf16(float* d, const uint32_t* a, const uint32_t* b) {
    asm volatile(
        "mma.sync.aligned.m16n8k16.row.col.f32.bf16.bf16.f32 "
        "{%0,%1,%2,%3}, {%4,%5,%6,%7}, {%8,%9}, {%0,%1,%2,%3};"
        : "+f"(d[0]), "+f"(d[1]), "+f"(d[2]), "+f"(d[3])
        : "r"(a[0]), "r"(a[1]), "r"(a[2]), "r"(a[3]), "r"(b[0]), "r"(b[1]));
}
__device__ __forceinline__ void cp16(uint32_t dst, const void* src) {
    asm volatile("cp.async.cg.shared.global [%0], [%1], 16;" :: "r"(dst), "l"(src));
}
__device__ __forceinline__ uint32_t pack_bf2(float x, float y) {
    __nv_bfloat162 h;
    h.x = __float2bfloat16(x); h.y = __float2bfloat16(y);
    return *(uint32_t*)&h;
}

// ================= hi/lo conversion kernels =================
__global__ void conv_hilo(const float* __restrict__ src,
                          __nv_bfloat16* __restrict__ hi, __nv_bfloat16* __restrict__ lo, int n) {
    int i = blockIdx.x * 256 + threadIdx.x;
    if (i >= n) return;
    float x = src[i];
    __nv_bfloat16 h = __float2bfloat16(x);
    hi[i] = h;
    lo[i] = __float2bfloat16(x - __bfloat162float(h));
}

// src [K][N] fp32 -> hi/lo [N][K] bf16
__global__ void conv_hilo_T(const float* __restrict__ src,
                            __nv_bfloat16* __restrict__ hi, __nv_bfloat16* __restrict__ lo,
                            int K, int N) {
    __shared__ float t[32][33];
    int bn = blockIdx.x * 32, bk = blockIdx.y * 32;
    int x = threadIdx.x, y = threadIdx.y;
    #pragma unroll
    for (int i = 0; i < 32; i += 8)
        t[y + i][x] = src[(long)(bk + y + i) * N + bn + x];
    __syncthreads();
    #pragma unroll
    for (int i = 0; i < 32; i += 8) {
        float v = t[x][y + i];
        long o = (long)(bn + y + i) * K + bk + x;
        __nv_bfloat16 h = __float2bfloat16(v);
        hi[o] = h;
        lo[o] = __float2bfloat16(v - __bfloat162float(h));
    }
}

// Q (post-rope) * SCALE -> hi/lo
__global__ void q_hilo() {
    long i = (long)blockIdx.x * 256 + threadIdx.x;
    if (i >= (long)BB * HH * QN * DD) return;
    float x = g_qrope[i] * SCALE;
    __nv_bfloat16 h = __float2bfloat16(x);
    gQ_hi[i] = h;
    gQ_lo[i] = __float2bfloat16(x - __bfloat162float(h));
}

// present K/V caches [0,KLEN) -> hi/lo
__global__ void kv_hilo(const float* __restrict__ kc, const float* __restrict__ vc) {
    long i = (long)blockIdx.x * 256 + threadIdx.x;
    if (i >= (long)BB * HKV * KLEN * DD) return;
    int d = (int)(i & (DD - 1));
    long t = i >> 7;
    int pos = (int)(t & (KLEN - 1));
    t >>= 11;
    long src = (t * MAXC + pos) * DD + d;
    float kx = kc[src];
    __nv_bfloat16 kh = __float2bfloat16(kx);
    gKc_hi[i] = kh;
    gKc_lo[i] = __float2bfloat16(kx - __bfloat162float(kh));
    float vx = vc[src];
    __nv_bfloat16 vh = __float2bfloat16(vx);
    gVc_hi[i] = vh;
    gVc_lo[i] = __float2bfloat16(vx - __bfloat162float(vh));
}

// ================= warp-MMA hi/lo GEMM (3-stage, swizzled, 1 sync/iter) =================
// Tile layout: 128 rows x 64B (32 bf16), 16B chunk swizzle: ch_phys = ch ^ ((row>>1)&3)
#define TILE_B  8192
#define STAGE_B (4 * TILE_B)              // Ahi,Alo,Bhi,Blo = 32768
#define NST     3
#define GEMM_SMEM (NST * STAGE_B)         // 98304

__device__ __forceinline__ uint32_t swz(int row, int ch) {
    return (uint32_t)(row * 64 + ((ch ^ ((row >> 1) & 3)) << 4));
}

__device__ __forceinline__ void fill_stage(
    uint32_t sb, int kt, int m0, int n0, int K,
    const __nv_bfloat16* Ahi, const __nv_bfloat16* Alo,
    const __nv_bfloat16* Bhi, const __nv_bfloat16* Blo, int tid)
{
    long k0 = (long)kt * 32;
    const __nv_bfloat16* bases[4] = {Ahi, Alo, Bhi, Blo};
    #pragma unroll
    for (int t = 0; t < 4; t++) {
        const __nv_bfloat16* bp = bases[t];
        int r0 = (t < 2) ? m0 : n0;
        #pragma unroll
        for (int i = 0; i < 2; i++) {
            int idx = tid + i * 256;
            int row = idx >> 2, ch = idx & 3;
            cp16(sb + t * TILE_B + swz(row, ch), bp + (long)(r0 + row) * K + k0 + ch * 8);
        }
    }
}

__global__ void __launch_bounds__(256, 2) gemm_mma(
    const __nv_bfloat16* __restrict__ Ahi, const __nv_bfloat16* __restrict__ Alo,
    const __nv_bfloat16* __restrict__ Bhi, const __nv_bfloat16* __restrict__ Blo,
    float* __restrict__ C, int M, int N, int K)
{
    extern __shared__ char smraw[];
    uint32_t s0 = smem_u32(smraw);
    int tid = threadIdx.x, lane = tid & 31, wid = tid >> 5;
    int wm = wid & 3, wn = wid >> 2;
    int m0 = blockIdx.y * 128, n0 = blockIdx.x * 128;

    float acc[2][8][4];
    #pragma unroll
    for (int i = 0; i < 2; i++)
        #pragma unroll
        for (int j = 0; j < 8; j++)
            #pragma unroll
            for (int k = 0; k < 4; k++) acc[i][j][k] = 0.f;

    int nk = K >> 5;
    fill_stage(s0, 0, m0, n0, K, Ahi, Alo, Bhi, Blo, tid);
    asm volatile("cp.async.commit_group;" ::: "memory");
    fill_stage(s0 + STAGE_B, 1, m0, n0, K, Ahi, Alo, Bhi, Blo, tid);
    asm volatile("cp.async.commit_group;" ::: "memory");

    // per-lane fragment coordinates
    int a_row = wm * 32 + (lane & 15);
    int a_cb  = lane >> 4;                 // chunk lsb for A
    int b_row = wn * 64 + (lane & 7) + (lane >> 4) * 8;
    int b_cb  = (lane >> 3) & 1;           // chunk lsb for B

    for (int kt = 0; kt < nk; kt++) {
        asm volatile("cp.async.wait_group 1;" ::: "memory");
        __syncthreads();

        // refill the stage consumed two iterations ago
        if (kt + 2 < nk)
            fill_stage(s0 + ((kt + 2) % NST) * STAGE_B, kt + 2, m0, n0, K, Ahi, Alo, Bhi, Blo, tid);
        asm volatile("cp.async.commit_group;" ::: "memory");

        uint32_t sb = s0 + (kt % NST) * STAGE_B;
        #pragma unroll
        for (int ks = 0; ks < 2; ks++) {
            uint32_t a[2][2][4];
            #pragma unroll
            for (int hl = 0; hl < 2; hl++)
                #pragma unroll
                for (int mt = 0; mt < 2; mt++) {
                    int row = a_row + mt * 16;
                    ldm_x4(a[hl][mt], sb + hl * TILE_B + swz(row, ks * 2 + a_cb));
                }
            #pragma unroll
            for (int np = 0; np < 4; np++) {
                uint32_t bh[4], bl[4];
                int row = b_row + np * 16;
                uint32_t bo = swz(row, ks * 2 + b_cb);
                ldm_x4(bh, sb + 2 * TILE_B + bo);
                ldm_x4(bl, sb + 3 * TILE_B + bo);
                #pragma unroll
                for (int mt = 0; mt < 2; mt++)
                    #pragma unroll
                    for (int nt = 0; nt < 2; nt++) {
                        float* d = acc[mt][np * 2 + nt];
                        mma_bf16(d, a[0][mt], &bh[nt * 2]);
                        mma_bf16(d, a[0][mt], &bl[nt * 2]);
                        mma_bf16(d, a[1][mt], &bh[nt * 2]);
                    }
            }
        }
    }

    int row0 = m0 + wm * 32 + (lane >> 2);
    int col0 = n0 + wn * 64 + (lane & 3) * 2;
    #pragma unroll
    for (int mt = 0; mt < 2; mt++)
        #pragma unroll
        for (int nt = 0; nt < 8; nt++) {
            float* d = acc[mt][nt];
            long r = row0 + mt * 16;
            long c = col0 + nt * 8;
            *(float2*)(C + r * N + c)       = make_float2(d[0], d[1]);
            *(float2*)(C + (r + 8) * N + c) = make_float2(d[2], d[3]);
        }
}

// ---------------- RMSNorm + RoPE + cache scatter ----------------
__global__ void qkv_post_kernel(const float* __restrict__ rope,
                                const int*   __restrict__ start,
                                const float* __restrict__ qw,
                                const float* __restrict__ kw,
                                float* __restrict__ out_k,
                                float* __restrict__ out_v)
{
    int slot = blockIdx.x;
    int q    = blockIdx.y;
    int b    = blockIdx.z;
    int tid  = threadIdx.x;
    long row = ((long)b * QN + q) * NQKV;
    float x = g_qkv[row + (long)slot * DD + tid];
    int pos = start[b] + q;

    if (slot >= 40) {
        int h = slot - 40;
        out_v[(((long)b * HKV + h) * MAXC + pos) * DD + tid] = x;
        return;
    }

    __shared__ float red[4];
    __shared__ float sm[DD];
    float v2 = x * x;
    #pragma unroll
    for (int m = 16; m; m >>= 1) v2 += __shfl_xor_sync(0xffffffffu, v2, m);
    if ((tid & 31) == 0) red[tid >> 5] = v2;
    __syncthreads();
    float tot = red[0] + red[1] + red[2] + red[3];
    float scl = rsqrtf(tot * (1.f / DD) + 1e-6f);
    const float* w = (slot < 32) ? qw : kw;
    sm[tid] = x * scl * w[tid];
    __syncthreads();

    int i = (tid < 64) ? tid : tid - 64;
    float c = rope[(long)pos * DD + i];
    float s = rope[(long)pos * DD + 64 + i];
    float x1 = sm[i], x2 = sm[i + 64];
    float o = (tid < 64) ? (x1 * c - x2 * s) : (x2 * c + x1 * s);

    if (slot < 32) {
        g_qrope[(((long)b * HH + slot) * QN + q) * DD + tid] = o;
    } else {
        int h = slot - 32;
        out_k[(((long)b * HKV + h) * MAXC + pos) * DD + tid] = o;
    }
}

// ================= tensor-core flash attention (bf16 hi/lo) =================
#define APITCHB 272
#define AQ 64
#define ATILE (AQ * APITCHB)               // 17408 per hi or lo
#define ATTN_SMEM (6 * ATILE)              // 104448

__device__ __forceinline__ void load_tile64(uint32_t dst,
    const __nv_bfloat16* hi, const __nv_bfloat16* lo, long rowbase, int tid)
{
    #pragma unroll
    for (int i = 0; i < 8; i++) {
        int idx = tid + i * 128;
        int row = idx >> 4, ch = idx & 15;
        uint32_t d = dst + row * APITCHB + ch * 16;
        const long off = rowbase + (long)row * DD + (ch << 3);
        cp16(d, hi + off);
        cp16(d + ATILE, lo + off);
    }
}

__global__ void __launch_bounds__(128, 2) attn_mma()
{
    extern __shared__ char smraw[];
    uint32_t sQ = smem_u32(smraw);
    uint32_t sK = sQ + 2 * ATILE;
    uint32_t sV = sK + 2 * ATILE;
    int tid = threadIdx.x, lane = tid & 31, w = tid >> 5;
    int qt = blockIdx.x, h = blockIdx.y, b = blockIdx.z;
    int kvh = h >> 2;
    int q0 = qt * 64;

    long qbase  = ((long)(b * HH + h) * QN + q0) * DD;
    long kvbase = (long)(b * HKV + kvh) * KLEN * DD;

    load_tile64(sQ, gQ_hi, gQ_lo, qbase, tid);
    load_tile64(sK, gKc_hi, gKc_lo, kvbase, tid);
    asm volatile("cp.async.commit_group;" ::: "memory");

    const int nc = 17 + qt;

    float O[16][4];
    #pragma unroll
    for (int i = 0; i < 16; i++)
        #pragma unroll
        for (int j = 0; j < 4; j++) O[i][j] = 0.f;
    float m0 = -1e30f, m1 = -1e30f, l0 = 0.f, l1 = 0.f;

    const int a_row  = w * 16 + (lane & 15);
    const int a_kb   = (lane >> 4) * 16;
    const int b_row  = (lane & 7) + (lane >> 4) * 8;
    const int b_kb   = ((lane >> 3) & 1) * 16;
    const int v_row  = lane & 15;
    const int v_col  = (lane >> 4) * 8;

    for (int c = 0; c < nc; c++) {
        int kb = c * 64;
        asm volatile("cp.async.wait_group 0;" ::: "memory");
        __syncthreads();

        load_tile64(sV, gVc_hi, gVc_lo, kvbase + (long)kb * DD, tid);
        asm volatile("cp.async.commit_group;" ::: "memory");

        // ---- S = Q K^T ----
        float S[8][4];
        #pragma unroll
        for (int j = 0; j < 8; j++)
            #pragma unroll
            for (int k = 0; k < 4; k++) S[j][k] = 0.f;

        #pragma unroll
        for (int ks = 0; ks < 8; ks++) {
            uint32_t ah[4], al[4];
            uint32_t qa = sQ + a_row * APITCHB + ks * 32 + a_kb;
            ldm_x4(ah, qa);
            ldm_x4(al, qa + ATILE);
            #pragma unroll
            for (int np = 0; np < 4; np++) {
                uint32_t bh[4], bl[4];
                uint32_t ka = sK + (np * 16 + b_row) * APITCHB + ks * 32 + b_kb;
                ldm_x4(bh, ka);
                ldm_x4(bl, ka + ATILE);
                #pragma unroll
                for (int nt = 0; nt < 2; nt++) {
                    float* d = S[np * 2 + nt];
                    mma_bf16(d, ah, &bh[nt * 2]);
                    mma_bf16(d, ah, &bl[nt * 2]);
                    mma_bf16(d, al, &bh[nt * 2]);
                }
            }
        }

        if (c == nc - 1) {
            int klim0 = PAST + q0 + w * 16 + (lane >> 2);
            int klim1 = klim0 + 8;
            #pragma unroll
            for (int j = 0; j < 8; j++) {
                int col = kb + j * 8 + (lane & 3) * 2;
                if (col > klim0)     S[j][0] = -1e30f;
                if (col + 1 > klim0) S[j][1] = -1e30f;
                if (col > klim1)     S[j][2] = -1e30f;
                if (col + 1 > klim1) S[j][3] = -1e30f;
            }
        }

        // ---- online softmax ----
        float mx0 = -1e30f, mx1 = -1e30f;
        #pragma unroll
        for (int j = 0; j < 8; j++) {
            mx0 = fmaxf(mx0, fmaxf(S[j][0], S[j][1]));
            mx1 = fmaxf(mx1, fmaxf(S[j][2], S[j][3]));
        }
        mx0 = fmaxf(mx0, __shfl_xor_sync(0xffffffffu, mx0, 1));
        mx0 = fmaxf(mx0, __shfl_xor_sync(0xffffffffu, mx0, 2));
        mx1 = fmaxf(mx1, __shfl_xor_sync(0xffffffffu, mx1, 1));
        mx1 = fmaxf(mx1, __shfl_xor_sync(0xffffffffu, mx1, 2));
        float mn0 = fmaxf(m0, mx0), mn1 = fmaxf(m1, mx1);
        float al0 = __expf(m0 - mn0), al1 = __expf(m1 - mn1);
        float r0 = 0.f, r1 = 0.f;
        #pragma unroll
        for (int j = 0; j < 8; j++) {
            S[j][0] = __expf(S[j][0] - mn0);
            S[j][1] = __expf(S[j][1] - mn0);
            S[j][2] = __expf(S[j][2] - mn1);
            S[j][3] = __expf(S[j][3] - mn1);
            r0 += S[j][0] + S[j][1];
            r1 += S[j][2] + S[j][3];
        }
        r0 += __shfl_xor_sync(0xffffffffu, r0, 1);
        r0 += __shfl_xor_sync(0xffffffffu, r0, 2);
        r1 += __shfl_xor_sync(0xffffffffu, r1, 1);
        r1 += __shfl_xor_sync(0xffffffffu, r1, 2);
        l0 = l0 * al0 + r0;
        l1 = l1 * al1 + r1;
        m0 = mn0; m1 = mn1;
        #pragma unroll
        for (int i = 0; i < 16; i++) {
            O[i][0] *= al0; O[i][1] *= al0;
            O[i][2] *= al1; O[i][3] *= al1;
        }

        // ---- P -> bf16 hi/lo A-frags ----
        uint32_t pa_h[4][4], pa_l[4][4];
        #pragma unroll
        for (int kt = 0; kt < 4; kt++) {
            int j0 = 2 * kt, j1 = 2 * kt + 1;
            float v00 = S[j0][0], v01 = S[j0][1], v02 = S[j0][2], v03 = S[j0][3];
            float v10 = S[j1][0], v11 = S[j1][1], v12 = S[j1][2], v13 = S[j1][3];
            pa_h[kt][0] = pack_bf2(v00, v01);
            pa_h[kt][1] = pack_bf2(v02, v03);
            pa_h[kt][2] = pack_bf2(v10, v11);
            pa_h[kt][3] = pack_bf2(v12, v13);
            __nv_bfloat162* hp;
            hp = (__nv_bfloat162*)&pa_h[kt][0];
            pa_l[kt][0] = pack_bf2(v00 - __bfloat162float(hp->x), v01 - __bfloat162float(hp->y));
            hp = (__nv_bfloat162*)&pa_h[kt][1];
            pa_l[kt][1] = pack_bf2(v02 - __bfloat162float(hp->x), v03 - __bfloat162float(hp->y));
            hp = (__nv_bfloat162*)&pa_h[kt][2];
            pa_l[kt][2] = pack_bf2(v10 - __bfloat162float(hp->x), v11 - __bfloat162float(hp->y));
            hp = (__nv_bfloat162*)&pa_h[kt][3];
            pa_l[kt][3] = pack_bf2(v12 - __bfloat162float(hp->x), v13 - __bfloat162float(hp->y));
        }

        __syncthreads();
        if (c + 1 < nc) {
            load_tile64(sK, gKc_hi, gKc_lo, kvbase + (long)(kb + 64) * DD, tid);
            asm volatile("cp.async.commit_group;" ::: "memory");
            asm volatile("cp.async.wait_group 1;" ::: "memory");
        } else {
            asm volatile("cp.async.wait_group 0;" ::: "memory");
        }
        __syncthreads();

        // ---- O += P V ----
        #pragma unroll
        for (int kt = 0; kt < 4; kt++) {
            #pragma unroll
            for (int np = 0; np < 8; np++) {
                uint32_t vh[4], vl[4];
                uint32_t va = sV + (kt * 16 + v_row) * APITCHB + (np * 16 + v_col) * 2;
                ldm_x4t(vh, va);
                ldm_x4t(vl, va + ATILE);
                #pragma unroll
                for (int nt = 0; nt < 2; nt++) {
                    float* d = O[np * 2 + nt];
                    mma_bf16(d, pa_h[kt], &vh[nt * 2]);
                    mma_bf16(d, pa_h[kt], &vl[nt * 2]);
                    mma_bf16(d, pa_l[kt], &vh[nt * 2]);
                }
            }
        }
        __syncthreads();
    }

    float inv0 = 1.f / l0, inv1 = 1.f / l1;
    int row0 = q0 + w * 16 + (lane >> 2);
    float* ob = g_attnO + ((long)(b * HH + h) * QN) * DD;
    #pragma unroll
    for (int np = 0; np < 16; np++) {
        int col = np * 8 + (lane & 3) * 2;
        *(float2*)(ob + (long)row0 * DD + col)       = make_float2(O[np][0] * inv0, O[np][1] * inv0);
        *(float2*)(ob + (long)(row0 + 8) * DD + col) = make_float2(O[np][2] * inv1, O[np][3] * inv1);
    }
}

// ---------------- group sum + hi/lo conversion ----------------
__global__ void group_sum_kernel()
{
    long i = (long)blockIdx.x * 256 + threadIdx.x;
    if (i >= (long)BB * QN * HKV * DD) return;
    int d = (int)(i & (DD - 1));
    long t = i >> 7;
    int kvh = (int)(t & (HKV - 1));
    t >>= 3;
    int q = (int)(t % QN);
    int b = (int)(t / QN);
    float sum = 0.f;
    #pragma unroll
    for (int g = 0; g < GROUPS; g++)
        sum += g_attnO[(((long)b * HH + kvh * GROUPS + g) * QN + q) * DD + d];
    __nv_bfloat16 h = __float2bfloat16(sum);
    gXo_hi[i] = h;
    gXo_lo[i] = __float2bfloat16(sum - __bfloat162float(h));
}

// ---------------- launch ----------------
static __nv_bfloat16* sym_addr_b(const void* sym) {
    void* p = nullptr;
    cudaGetSymbolAddress(&p, sym);
    return (__nv_bfloat16*)p;
}
static float* sym_addr_f(const void* sym) {
    void* p = nullptr;
    cudaGetSymbolAddress(&p, sym);
    return (float*)p;
}

extern "C" void kernel_launch(void* const* d_in, const int* in_sizes, int n_in,
                              void* d_out, int out_size)
{
    const float* hidden = (const float*)d_in[0];
    const float* kcache = (const float*)d_in[1];
    const float* vcache = (const float*)d_in[2];
    const float* rope   = (const float*)d_in[3];
    const int*   start  = (const int*)  d_in[5];
    const float* w_qkv  = (const float*)d_in[6];
    const float* w_o    = (const float*)d_in[7];
    const float* qw     = (const float*)d_in[8];
    const float* kw     = (const float*)d_in[9];

    float* out      = (float*)d_out;
    float* out_attn = out;
    float* out_k    = out + OUT_SZ1;
    float* out_v    = out + OUT_SZ1 + CACHE_SZ;

    float* s_qkv = sym_addr_f(g_qkv);
    __nv_bfloat16* sA_hi = sym_addr_b(gA_hi);  __nv_bfloat16* sA_lo = sym_addr_b(gA_lo);
    __nv_bfloat16* sWq_hi = sym_addr_b(gWq_hi); __nv_bfloat16* sWq_lo = sym_addr_b(gWq_lo);
    __nv_bfloat16* sWo_hi = sym_addr_b(gWo_hi); __nv_bfloat16* sWo_lo = sym_addr_b(gWo_lo);
    __nv_bfloat16* sXo_hi = sym_addr_b(gXo_hi); __nv_bfloat16* sXo_lo = sym_addr_b(gXo_lo);

    cudaFuncSetAttribute(gemm_mma, cudaFuncAttributeMaxDynamicSharedMemorySize, GEMM_SMEM);
    cudaFuncSetAttribute(attn_mma, cudaFuncAttributeMaxDynamicSharedMemorySize, ATTN_SMEM);

    // 1. present caches
    cudaMemcpyAsync(out_k, kcache, (size_t)CACHE_SZ * sizeof(float), cudaMemcpyDeviceToDevice, 0);
    cudaMemcpyAsync(out_v, vcache, (size_t)CACHE_SZ * sizeof(float), cudaMemcpyDeviceToDevice, 0);

    // 2. hi/lo conversions for projections
    conv_hilo<<<(BB*QN*HID + 255) / 256, 256>>>(hidden, sA_hi, sA_lo, BB*QN*HID);
    conv_hilo_T<<<dim3(NQKV / 32, HID / 32), dim3(32, 8)>>>(w_qkv, sWq_hi, sWq_lo, HID, NQKV);
    conv_hilo_T<<<dim3(HID / 32, (HKV*DD) / 32), dim3(32, 8)>>>(w_o, sWo_hi, sWo_lo, HKV*DD, HID);

    // 3. QKV projection
    gemm_mma<<<dim3(NQKV / 128, (BB*QN) / 128), 256, GEMM_SMEM>>>(
        sA_hi, sA_lo, sWq_hi, sWq_lo, s_qkv, BB*QN, NQKV, HID);

    // 4. RMSNorm + RoPE + scatter
    qkv_post_kernel<<<dim3(48, QN, BB), 128>>>(rope, start, qw, kw, out_k, out_v);

    // 5. attention operand conversions
    q_hilo<<<(BB*HH*QN*DD + 255) / 256, 256>>>();
    kv_hilo<<<(BB*HKV*KLEN*DD + 255) / 256, 256>>>(out_k, out_v);

    // 6. tensor-core flash attention
    attn_mma<<<dim3(QN / 64, HH, BB), 128, ATTN_SMEM>>>();

    // 7. group-sum + hi/lo
    group_sum_kernel<<<(BB*QN*HKV*DD + 255) / 256, 256>>>();

    // 8. output projection
    gemm_mma<<<dim3(HID / 128, (BB*QN) / 128), 256, GEMM_SMEM>>>(
        sXo_hi, sXo_lo, sWo_hi, sWo_lo, out_attn, BB*QN, HID, HKV*DD);
}

// round 7
// speedup vs baseline: 4.7907x; 1.0239x over previous
#include <cuda_runtime.h>
#include <cuda_bf16.h>
#include <cstdint>

// ---------------- problem constants ----------------
#define BB    2
#define QN    1024
#define PAST  1024
#define MAXC  4096
#define HH    32
#define HKV   8
#define DD    128
#define HID   4096
#define KLEN  (PAST + QN)          // 2048
#define NQKV  ((HH + 2*HKV) * DD)  // 6144
#define GROUPS (HH / HKV)
#define SCALE 0.08838834764831845f

#define OUT_SZ1 (BB*QN*HID)
#define CACHE_SZ (BB*HKV*MAXC*DD)

// ---------------- scratch (device globals) ----------------
__device__ __align__(16) float g_qkv  [BB*QN*NQKV];
__device__ __align__(16) float g_qrope[BB*HH*QN*DD];
__device__ __align__(16) float g_attnO[BB*HH*QN*DD];

__device__ __align__(16) __nv_bfloat16 gA_hi [BB*QN*HID];
__device__ __align__(16) __nv_bfloat16 gA_lo [BB*QN*HID];
__device__ __align__(16) __nv_bfloat16 gWq_hi[NQKV*HID];
__device__ __align__(16) __nv_bfloat16 gWq_lo[NQKV*HID];
__device__ __align__(16) __nv_bfloat16 gWo_hi[HID*HKV*DD];
__device__ __align__(16) __nv_bfloat16 gWo_lo[HID*HKV*DD];
__device__ __align__(16) __nv_bfloat16 gXo_hi[BB*QN*HKV*DD];
__device__ __align__(16) __nv_bfloat16 gXo_lo[BB*QN*HKV*DD];

// attention bf16 hi/lo operands
__device__ __align__(16) __nv_bfloat16 gQ_hi [BB*HH*QN*DD];
__device__ __align__(16) __nv_bfloat16 gQ_lo [BB*HH*QN*DD];
__device__ __align__(16) __nv_bfloat16 gKc_hi[BB*HKV*KLEN*DD];
__device__ __align__(16) __nv_bfloat16 gKc_lo[BB*HKV*KLEN*DD];
__device__ __align__(16) __nv_bfloat16 gVc_hi[BB*HKV*KLEN*DD];
__device__ __align__(16) __nv_bfloat16 gVc_lo[BB*HKV*KLEN*DD];

// ================= PTX helpers (sm_80+ portable subset) =================
__device__ __forceinline__ uint32_t smem_u32(const void* p) {
    uint32_t a;
    asm("{ .reg .u64 t; cvta.to.shared.u64 t, %1; cvt.u32.u64 %0, t; }" : "=r"(a) : "l"(p));
    return a;
}
__device__ __forceinline__ void ldm_x4(uint32_t* r, uint32_t addr) {
    asm volatile("ldmatrix.sync.aligned.m8n8.x4.shared.b16 {%0,%1,%2,%3}, [%4];"
                 : "=r"(r[0]), "=r"(r[1]), "=r"(r[2]), "=r"(r[3]) : "r"(addr));
}
__device__ __forceinline__ void ldm_x4t(uint32_t* r, uint32_t addr) {
    asm volatile("ldmatrix.sync.aligned.m8n8.x4.trans.shared.b16 {%0,%1,%2,%3}, [%4];"
                 : "=r"(r[0]), "=r"(r[1]), "=r"(r[2]), "=r"(r[3]) : "r"(addr));
}
__device__ __forceinline__ void mma_bf16(float* d, const uint32_t* a, const uint32_t* b) {
    asm volatile(
        "mma.sync.aligned.m16n8k16.row.col.f32.bf16.bf16.f32 "
        "{%0,%1,%2,%3}, {%4,%5,%6,%7}, {%8,%9}, {%0,%1,%2,%3};"
        : "+f"(d[0]), "+f"(d[1]), "+f"(d[2]), "+f"(d[3])
        : "r"(a[0]), "r"(a[1]), "r"(a[2]), "r"(a[3]), "r"(b[0]), "r"(b[1]));
}
__device__ __forceinline__ void cp16(uint32_t dst, const void* src) {
    asm volatile("cp.async.cg.shared.global [%0], [%1], 16;" :: "r"(dst), "l"(src));
}
__device__ __forceinline__ uint32_t pack_bf2(float x, float y) {
    __nv_bfloat162 h;
    h.x = __float2bfloat16(x); h.y = __float2bfloat16(y);
    return *(uint32_t*)&h;
}

// ================= hi/lo conversion kernels =================
__global__ void conv_hilo(const float* __restrict__ src,
                          __nv_bfloat16* __restrict__ hi, __nv_bfloat16* __restrict__ lo, int n) {
    int i = blockIdx.x * 256 + threadIdx.x;
    if (i >= n) return;
    float x = src[i];
    __nv_bfloat16 h = __float2bfloat16(x);
    hi[i] = h;
    lo[i] = __float2bfloat16(x - __bfloat162float(h));
}

// src [K][N] fp32 -> hi/lo [N][K] bf16
__global__ void conv_hilo_T(const float* __restrict__ src,
                            __nv_bfloat16* __restrict__ hi, __nv_bfloat16* __restrict__ lo,
                            int K, int N) {
    __shared__ float t[32][33];
    int bn = blockIdx.x * 32, bk = blockIdx.y * 32;
    int x = threadIdx.x, y = threadIdx.y;
    #pragma unroll
    for (int i = 0; i < 32; i += 8)
        t[y + i][x] = src[(long)(bk + y + i) * N + bn + x];
    __syncthreads();
    #pragma unroll
    for (int i = 0; i < 32; i += 8) {
        float v = t[x][y + i];
        long o = (long)(bn + y + i) * K + bk + x;
        __nv_bfloat16 h = __float2bfloat16(v);
        hi[o] = h;
        lo[o] = __float2bfloat16(v - __bfloat162float(h));
    }
}

// Q (post-rope) * SCALE -> hi/lo
__global__ void q_hilo() {
    long i = (long)blockIdx.x * 256 + threadIdx.x;
    if (i >= (long)BB * HH * QN * DD) return;
    float x = g_qrope[i] * SCALE;
    __nv_bfloat16 h = __float2bfloat16(x);
    gQ_hi[i] = h;
    gQ_lo[i] = __float2bfloat16(x - __bfloat162float(h));
}

// present K/V caches [0,KLEN) -> hi/lo
__global__ void kv_hilo(const float* __restrict__ kc, const float* __restrict__ vc) {
    long i = (long)blockIdx.x * 256 + threadIdx.x;
    if (i >= (long)BB * HKV * KLEN * DD) return;
    int d = (int)(i & (DD - 1));
    long t = i >> 7;
    int pos = (int)(t & (KLEN - 1));
    t >>= 11;
    long src = (t * MAXC + pos) * DD + d;
    float kx = kc[src];
    __nv_bfloat16 kh = __float2bfloat16(kx);
    gKc_hi[i] = kh;
    gKc_lo[i] = __float2bfloat16(kx - __bfloat162float(kh));
    float vx = vc[src];
    __nv_bfloat16 vh = __float2bfloat16(vx);
    gVc_hi[i] = vh;
    gVc_lo[i] = __float2bfloat16(vx - __bfloat162float(vh));
}

// ================= warp-MMA hi/lo GEMM (3-stage, swizzled, 64x64 warp tile) =================
// Tile layout: 128 rows x 64B (32 bf16), 16B chunk swizzle: ch_phys = ch ^ ((row>>1)&3)
#define TILE_B  8192
#define STAGE_B (4 * TILE_B)              // Ahi,Alo,Bhi,Blo = 32768
#define NST     3
#define GEMM_SMEM (NST * STAGE_B)         // 98304

__device__ __forceinline__ uint32_t swz(int row, int ch) {
    return (uint32_t)(row * 64 + ((ch ^ ((row >> 1) & 3)) << 4));
}

__device__ __forceinline__ void fill_stage(
    uint32_t sb, int kt, int m0, int n0, int K,
    const __nv_bfloat16* Ahi, const __nv_bfloat16* Alo,
    const __nv_bfloat16* Bhi, const __nv_bfloat16* Blo, int tid)
{
    long k0 = (long)kt * 32;
    const __nv_bfloat16* bases[4] = {Ahi, Alo, Bhi, Blo};
    #pragma unroll
    for (int t = 0; t < 4; t++) {
        const __nv_bfloat16* bp = bases[t];
        int r0 = (t < 2) ? m0 : n0;
        #pragma unroll
        for (int i = 0; i < 4; i++) {
            int idx = tid + i * 128;          // 0..511
            int row = idx >> 2, ch = idx & 3;
            cp16(sb + t * TILE_B + swz(row, ch), bp + (long)(r0 + row) * K + k0 + ch * 8);
        }
    }
}

__global__ void __launch_bounds__(128, 2) gemm_mma(
    const __nv_bfloat16* __restrict__ Ahi, const __nv_bfloat16* __restrict__ Alo,
    const __nv_bfloat16* __restrict__ Bhi, const __nv_bfloat16* __restrict__ Blo,
    float* __restrict__ C, int M, int N, int K)
{
    extern __shared__ char smraw[];
    uint32_t s0 = smem_u32(smraw);
    int tid = threadIdx.x, lane = tid & 31, wid = tid >> 5;
    int wm = wid & 1, wn = wid >> 1;          // 2 x 2 warps, 64x64 tiles
    int m0 = blockIdx.y * 128, n0 = blockIdx.x * 128;

    float acc[4][8][4];
    #pragma unroll
    for (int i = 0; i < 4; i++)
        #pragma unroll
        for (int j = 0; j < 8; j++)
            #pragma unroll
            for (int k = 0; k < 4; k++) acc[i][j][k] = 0.f;

    int nk = K >> 5;
    fill_stage(s0, 0, m0, n0, K, Ahi, Alo, Bhi, Blo, tid);
    asm volatile("cp.async.commit_group;" ::: "memory");
    fill_stage(s0 + STAGE_B, 1, m0, n0, K, Ahi, Alo, Bhi, Blo, tid);
    asm volatile("cp.async.commit_group;" ::: "memory");

    // per-lane fragment coordinates
    int a_row = wm * 64 + (lane & 15);
    int a_cb  = lane >> 4;                 // chunk lsb for A
    int b_row = wn * 64 + (lane & 7) + (lane >> 4) * 8;
    int b_cb  = (lane >> 3) & 1;           // chunk lsb for B

    for (int kt = 0; kt < nk; kt++) {
        asm volatile("cp.async.wait_group 1;" ::: "memory");
        __syncthreads();

        if (kt + 2 < nk)
            fill_stage(s0 + ((kt + 2) % NST) * STAGE_B, kt + 2, m0, n0, K, Ahi, Alo, Bhi, Blo, tid);
        asm volatile("cp.async.commit_group;" ::: "memory");

        uint32_t sb = s0 + (kt % NST) * STAGE_B;
        #pragma unroll
        for (int ks = 0; ks < 2; ks++) {
            uint32_t a[2][4][4];      // [hi/lo][mtile][4]
            #pragma unroll
            for (int hl = 0; hl < 2; hl++)
                #pragma unroll
                for (int mt = 0; mt < 4; mt++)
                    ldm_x4(a[hl][mt], sb + hl * TILE_B + swz(a_row + mt * 16, ks * 2 + a_cb));
            #pragma unroll
            for (int np = 0; np < 4; np++) {
                uint32_t bh[4], bl[4];
                uint32_t bo = swz(b_row + np * 16, ks * 2 + b_cb);
                ldm_x4(bh, sb + 2 * TILE_B + bo);
                ldm_x4(bl, sb + 3 * TILE_B + bo);
                #pragma unroll
                for (int mt = 0; mt < 4; mt++)
                    #pragma unroll
                    for (int nt = 0; nt < 2; nt++) {
                        float* d = acc[mt][np * 2 + nt];
                        mma_bf16(d, a[0][mt], &bh[nt * 2]);
                        mma_bf16(d, a[0][mt], &bl[nt * 2]);
                        mma_bf16(d, a[1][mt], &bh[nt * 2]);
                    }
            }
        }
    }

    int row0 = m0 + wm * 64 + (lane >> 2);
    int col0 = n0 + wn * 64 + (lane & 3) * 2;
    #pragma unroll
    for (int mt = 0; mt < 4; mt++)
        #pragma unroll
        for (int nt = 0; nt < 8; nt++) {
            float* d = acc[mt][nt];
            long r = row0 + mt * 16;
            long c = col0 + nt * 8;
            *(float2*)(C + r * N + c)       = make_float2(d[0], d[1]);
            *(float2*)(C + (r + 8) * N + c) = make_float2(d[2], d[3]);
        }
}

// ---------------- RMSNorm + RoPE + cache scatter ----------------
__global__ void qkv_post_kernel(const float* __restrict__ rope,
                                const int*   __restrict__ start,
                                const float* __restrict__ qw,
                                const float* __restrict__ kw,
                                float* __restrict__ out_k,
                                float* __restrict__ out_v)
{
    int slot = blockIdx.x;
    int q    = blockIdx.y;
    int b    = blockIdx.z;
    int tid  = threadIdx.x;
    long row = ((long)b * QN + q) * NQKV;
    float x = g_qkv[row + (long)slot * DD + tid];
    int pos = start[b] + q;

    if (slot >= 40) {
        int h = slot - 40;
        out_v[(((long)b * HKV + h) * MAXC + pos) * DD + tid] = x;
        return;
    }

    __shared__ float red[4];
    __shared__ float sm[DD];
    float v2 = x * x;
    #pragma unroll
    for (int m = 16; m; m >>= 1) v2 += __shfl_xor_sync(0xffffffffu, v2, m);
    if ((tid & 31) == 0) red[tid >> 5] = v2;
    __syncthreads();
    float tot = red[0] + red[1] + red[2] + red[3];
    float scl = rsqrtf(tot * (1.f / DD) + 1e-6f);
    const float* w = (slot < 32) ? qw : kw;
    sm[tid] = x * scl * w[tid];
    __syncthreads();

    int i = (tid < 64) ? tid : tid - 64;
    float c = rope[(long)pos * DD + i];
    float s = rope[(long)pos * DD + 64 + i];
    float x1 = sm[i], x2 = sm[i + 64];
    float o = (tid < 64) ? (x1 * c - x2 * s) : (x2 * c + x1 * s);

    if (slot < 32) {
        g_qrope[(((long)b * HH + slot) * QN + q) * DD + tid] = o;
    } else {
        int h = slot - 32;
        out_k[(((long)b * HKV + h) * MAXC + pos) * DD + tid] = o;
    }
}

// ================= tensor-core flash attention (bf16 hi/lo) =================
#define APITCHB 272
#define AQ 64
#define ATILE (AQ * APITCHB)               // 17408 per hi or lo
#define ATTN_SMEM (6 * ATILE)              // 104448

__device__ __forceinline__ void load_tile64(uint32_t dst,
    const __nv_bfloat16* hi, const __nv_bfloat16* lo, long rowbase, int tid)
{
    #pragma unroll
    for (int i = 0; i < 8; i++) {
        int idx = tid + i * 128;
        int row = idx >> 4, ch = idx & 15;
        uint32_t d = dst + row * APITCHB + ch * 16;
        const long off = rowbase + (long)row * DD + (ch << 3);
        cp16(d, hi + off);
        cp16(d + ATILE, lo + off);
    }
}

__global__ void __launch_bounds__(128, 2) attn_mma()
{
    extern __shared__ char smraw[];
    uint32_t sQ = smem_u32(smraw);
    uint32_t sK = sQ + 2 * ATILE;
    uint32_t sV = sK + 2 * ATILE;
    int tid = threadIdx.x, lane = tid & 31, w = tid >> 5;
    int qt = blockIdx.x, h = blockIdx.y, b = blockIdx.z;
    int kvh = h >> 2;
    int q0 = qt * 64;

    long qbase  = ((long)(b * HH + h) * QN + q0) * DD;
    long kvbase = (long)(b * HKV + kvh) * KLEN * DD;

    load_tile64(sQ, gQ_hi, gQ_lo, qbase, tid);
    load_tile64(sK, gKc_hi, gKc_lo, kvbase, tid);
    asm volatile("cp.async.commit_group;" ::: "memory");

    const int nc = 17 + qt;

    float O[16][4];
    #pragma unroll
    for (int i = 0; i < 16; i++)
        #pragma unroll
        for (int j = 0; j < 4; j++) O[i][j] = 0.f;
    float m0 = -1e30f, m1 = -1e30f, l0 = 0.f, l1 = 0.f;

    const int a_row  = w * 16 + (lane & 15);
    const int a_kb   = (lane >> 4) * 16;
    const int b_row  = (lane & 7) + (lane >> 4) * 8;
    const int b_kb   = ((lane >> 3) & 1) * 16;
    const int v_row  = lane & 15;
    const int v_col  = (lane >> 4) * 8;

    for (int c = 0; c < nc; c++) {
        int kb = c * 64;
        asm volatile("cp.async.wait_group 0;" ::: "memory");
        __syncthreads();

        load_tile64(sV, gVc_hi, gVc_lo, kvbase + (long)kb * DD, tid);
        asm volatile("cp.async.commit_group;" ::: "memory");

        // ---- S = Q K^T ----
        float S[8][4];
        #pragma unroll
        for (int j = 0; j < 8; j++)
            #pragma unroll
            for (int k = 0; k < 4; k++) S[j][k] = 0.f;

        #pragma unroll
        for (int ks = 0; ks < 8; ks++) {
            uint32_t ah[4], al[4];
            uint32_t qa = sQ + a_row * APITCHB + ks * 32 + a_kb;
            ldm_x4(ah, qa);
            ldm_x4(al, qa + ATILE);
            #pragma unroll
            for (int np = 0; np < 4; np++) {
                uint32_t bh[4], bl[4];
                uint32_t ka = sK + (np * 16 + b_row) * APITCHB + ks * 32 + b_kb;
                ldm_x4(bh, ka);
                ldm_x4(bl, ka + ATILE);
                #pragma unroll
                for (int nt = 0; nt < 2; nt++) {
                    float* d = S[np * 2 + nt];
                    mma_bf16(d, ah, &bh[nt * 2]);
                    mma_bf16(d, ah, &bl[nt * 2]);
                    mma_bf16(d, al, &bh[nt * 2]);
                }
            }
        }

        if (c == nc - 1) {
            int klim0 = PAST + q0 + w * 16 + (lane >> 2);
            int klim1 = klim0 + 8;
            #pragma unroll
            for (int j = 0; j < 8; j++) {
                int col = kb + j * 8 + (lane & 3) * 2;
                if (col > klim0)     S[j][0] = -1e30f;
                if (col + 1 > klim0) S[j][1] = -1e30f;
                if (col > klim1)     S[j][2] = -1e30f;
                if (col + 1 > klim1) S[j][3] = -1e30f;
            }
        }

        // ---- online softmax ----
        float mx0 = -1e30f, mx1 = -1e30f;
        #pragma unroll
        for (int j = 0; j < 8; j++) {
            mx0 = fmaxf(mx0, fmaxf(S[j][0], S[j][1]));
            mx1 = fmaxf(mx1, fmaxf(S[j][2], S[j][3]));
        }
        mx0 = fmaxf(mx0, __shfl_xor_sync(0xffffffffu, mx0, 1));
        mx0 = fmaxf(mx0, __shfl_xor_sync(0xffffffffu, mx0, 2));
        mx1 = fmaxf(mx1, __shfl_xor_sync(0xffffffffu, mx1, 1));
        mx1 = fmaxf(mx1, __shfl_xor_sync(0xffffffffu, mx1, 2));
        float mn0 = fmaxf(m0, mx0), mn1 = fmaxf(m1, mx1);
        float al0 = __expf(m0 - mn0), al1 = __expf(m1 - mn1);
        float r0 = 0.f, r1 = 0.f;
        #pragma unroll
        for (int j = 0; j < 8; j++) {
            S[j][0] = __expf(S[j][0] - mn0);
            S[j][1] = __expf(S[j][1] - mn0);
            S[j][2] = __expf(S[j][2] - mn1);
            S[j][3] = __expf(S[j][3] - mn1);
            r0 += S[j][0] + S[j][1];
            r1 += S[j][2] + S[j][3];
        }
        r0 += __shfl_xor_sync(0xffffffffu, r0, 1);
        r0 += __shfl_xor_sync(0xffffffffu, r0, 2);
        r1 += __shfl_xor_sync(0xffffffffu, r1, 1);
        r1 += __shfl_xor_sync(0xffffffffu, r1, 2);
        l0 = l0 * al0 + r0;
        l1 = l1 * al1 + r1;
        m0 = mn0; m1 = mn1;
        #pragma unroll
        for (int i = 0; i < 16; i++) {
            O[i][0] *= al0; O[i][1] *= al0;
            O[i][2] *= al1; O[i][3] *= al1;
        }

        // ---- P -> bf16 hi/lo A-frags ----
        uint32_t pa_h[4][4], pa_l[4][4];
        #pragma unroll
        for (int kt = 0; kt < 4; kt++) {
            int j0 = 2 * kt, j1 = 2 * kt + 1;
            float v00 = S[j0][0], v01 = S[j0][1], v02 = S[j0][2], v03 = S[j0][3];
            float v10 = S[j1][0], v11 = S[j1][1], v12 = S[j1][2], v13 = S[j1][3];
            pa_h[kt][0] = pack_bf2(v00, v01);
            pa_h[kt][1] = pack_bf2(v02, v03);
            pa_h[kt][2] = pack_bf2(v10, v11);
            pa_h[kt][3] = pack_bf2(v12, v13);
            __nv_bfloat162* hp;
            hp = (__nv_bfloat162*)&pa_h[kt][0];
            pa_l[kt][0] = pack_bf2(v00 - __bfloat162float(hp->x), v01 - __bfloat162float(hp->y));
            hp = (__nv_bfloat162*)&pa_h[kt][1];
            pa_l[kt][1] = pack_bf2(v02 - __bfloat162float(hp->x), v03 - __bfloat162float(hp->y));
            hp = (__nv_bfloat162*)&pa_h[kt][2];
            pa_l[kt][2] = pack_bf2(v10 - __bfloat162float(hp->x), v11 - __bfloat162float(hp->y));
            hp = (__nv_bfloat162*)&pa_h[kt][3];
            pa_l[kt][3] = pack_bf2(v12 - __bfloat162float(hp->x), v13 - __bfloat162float(hp->y));
        }

        __syncthreads();
        if (c + 1 < nc) {
            load_tile64(sK, gKc_hi, gKc_lo, kvbase + (long)(kb + 64) * DD, tid);
            asm volatile("cp.async.commit_group;" ::: "memory");
            asm volatile("cp.async.wait_group 1;" ::: "memory");
        } else {
            asm volatile("cp.async.wait_group 0;" ::: "memory");
        }
        __syncthreads();

        // ---- O += P V ----
        #pragma unroll
        for (int kt = 0; kt < 4; kt++) {
            #pragma unroll
            for (int np = 0; np < 8; np++) {
                uint32_t vh[4], vl[4];
                uint32_t va = sV + (kt * 16 + v_row) * APITCHB + (np * 16 + v_col) * 2;
                ldm_x4t(vh, va);
                ldm_x4t(vl, va + ATILE);
                #pragma unroll
                for (int nt = 0; nt < 2; nt++) {
                    float* d = O[np * 2 + nt];
                    mma_bf16(d, pa_h[kt], &vh[nt * 2]);
                    mma_bf16(d, pa_h[kt], &vl[nt * 2]);
                    mma_bf16(d, pa_l[kt], &vh[nt * 2]);
                }
            }
        }
        __syncthreads();
    }

    float inv0 = 1.f / l0, inv1 = 1.f / l1;
    int row0 = q0 + w * 16 + (lane >> 2);
    float* ob = g_attnO + ((long)(b * HH + h) * QN) * DD;
    #pragma unroll
    for (int np = 0; np < 16; np++) {
        int col = np * 8 + (lane & 3) * 2;
        *(float2*)(ob + (long)row0 * DD + col)       = make_float2(O[np][0] * inv0, O[np][1] * inv0);
        *(float2*)(ob + (long)(row0 + 8) * DD + col) = make_float2(O[np][2] * inv1, O[np][3] * inv1);
    }
}

// ---------------- group sum + hi/lo conversion ----------------
__global__ void group_sum_kernel()
{
    long i = (long)blockIdx.x * 256 + threadIdx.x;
    if (i >= (long)BB * QN * HKV * DD) return;
    int d = (int)(i & (DD - 1));
    long t = i >> 7;
    int kvh = (int)(t & (HKV - 1));
    t >>= 3;
    int q = (int)(t % QN);
    int b = (int)(t / QN);
    float sum = 0.f;
    #pragma unroll
    for (int g = 0; g < GROUPS; g++)
        sum += g_attnO[(((long)b * HH + kvh * GROUPS + g) * QN + q) * DD + d];
    __nv_bfloat16 h = __float2bfloat16(sum);
    gXo_hi[i] = h;
    gXo_lo[i] = __float2bfloat16(sum - __bfloat162float(h));
}

// ---------------- launch ----------------
static __nv_bfloat16* sym_addr_b(const void* sym) {
    void* p = nullptr;
    cudaGetSymbolAddress(&p, sym);
    return (__nv_bfloat16*)p;
}
static float* sym_addr_f(const void* sym) {
    void* p = nullptr;
    cudaGetSymbolAddress(&p, sym);
    return (float*)p;
}

extern "C" void kernel_launch(void* const* d_in, const int* in_sizes, int n_in,
                              void* d_out, int out_size)
{
    const float* hidden = (const float*)d_in[0];
    const float* kcache = (const float*)d_in[1];
    const float* vcache = (const float*)d_in[2];
    const float* rope   = (const float*)d_in[3];
    const int*   start  = (const int*)  d_in[5];
    const float* w_qkv  = (const float*)d_in[6];
    const float* w_o    = (const float*)d_in[7];
    const float* qw     = (const float*)d_in[8];
    const float* kw     = (const float*)d_in[9];

    float* out      = (float*)d_out;
    float* out_attn = out;
    float* out_k    = out + OUT_SZ1;
    float* out_v    = out + OUT_SZ1 + CACHE_SZ;

    float* s_qkv = sym_addr_f(g_qkv);
    __nv_bfloat16* sA_hi = sym_addr_b(gA_hi);  __nv_bfloat16* sA_lo = sym_addr_b(gA_lo);
    __nv_bfloat16* sWq_hi = sym_addr_b(gWq_hi); __nv_bfloat16* sWq_lo = sym_addr_b(gWq_lo);
    __nv_bfloat16* sWo_hi = sym_addr_b(gWo_hi); __nv_bfloat16* sWo_lo = sym_addr_b(gWo_lo);
    __nv_bfloat16* sXo_hi = sym_addr_b(gXo_hi); __nv_bfloat16* sXo_lo = sym_addr_b(gXo_lo);

    cudaFuncSetAttribute(gemm_mma, cudaFuncAttributeMaxDynamicSharedMemorySize, GEMM_SMEM);
    cudaFuncSetAttribute(attn_mma, cudaFuncAttributeMaxDynamicSharedMemorySize, ATTN_SMEM);

    // 1. present caches
    cudaMemcpyAsync(out_k, kcache, (size_t)CACHE_SZ * sizeof(float), cudaMemcpyDeviceToDevice, 0);
    cudaMemcpyAsync(out_v, vcache, (size_t)CACHE_SZ * sizeof(float), cudaMemcpyDeviceToDevice, 0);

    // 2. hi/lo conversions for projections
    conv_hilo<<<(BB*QN*HID + 255) / 256, 256>>>(hidden, sA_hi, sA_lo, BB*QN*HID);
    conv_hilo_T<<<dim3(NQKV / 32, HID / 32), dim3(32, 8)>>>(w_qkv, sWq_hi, sWq_lo, HID, NQKV);
    conv_hilo_T<<<dim3(HID / 32, (HKV*DD) / 32), dim3(32, 8)>>>(w_o, sWo_hi, sWo_lo, HKV*DD, HID);

    // 3. QKV projection
    gemm_mma<<<dim3(NQKV / 128, (BB*QN) / 128), 128, GEMM_SMEM>>>(
        sA_hi, sA_lo, sWq_hi, sWq_lo, s_qkv, BB*QN, NQKV, HID);

    // 4. RMSNorm + RoPE + scatter
    qkv_post_kernel<<<dim3(48, QN, BB), 128>>>(rope, start, qw, kw, out_k, out_v);

    // 5. attention operand conversions
    q_hilo<<<(BB*HH*QN*DD + 255) / 256, 256>>>();
    kv_hilo<<<(BB*HKV*KLEN*DD + 255) / 256, 256>>>(out_k, out_v);

    // 6. tensor-core flash attention
    attn_mma<<<dim3(QN / 64, HH, BB), 128, ATTN_SMEM>>>();

    // 7. group-sum + hi/lo
    group_sum_kernel<<<(BB*QN*HKV*DD + 255) / 256, 256>>>();

    // 8. output projection
    gemm_mma<<<dim3(HID / 128, (BB*QN) / 128), 128, GEMM_SMEM>>>(
        sXo_hi, sXo_lo, sWo_hi, sWo_lo, out_attn, BB*QN, HID, HKV*DD);
}